// round 7
// baseline (speedup 1.0000x reference)
#include <cuda_runtime.h>
#include <cuda_bf16.h>
#include <cstdint>

#define N_NODES 100000
#define N_EDGES 1600000
#define CH 128          // IN_CH = HEADS*HID = OUT_CH = 128
#define HEADS 4
#define HID 32
#define NEG_SLOPE 0.2f
#define NBLK 148
#define CBS 1024

// ---------------- scratch (static device globals; no allocation) ----------------
__device__ float g_h[(size_t)N_NODES * CH];       // x @ W (51.2 MB)
__device__ float g_asrc[(size_t)N_NODES * HEADS];
__device__ float g_adst[(size_t)N_NODES * HEADS];
__device__ int   g_deg[N_NODES];
__device__ int   g_off[N_NODES];
__device__ int   g_cur[N_NODES];
__device__ int   g_srcs[N_EDGES];
__device__ int   g_bsum[NBLK];
__device__ unsigned g_c[8];                        // grid-barrier counters (zero-init)
// pre-swizzled bf16 hi/lo images of W^T and lin_w^T ([n][k] layout, 32KB each)
__device__ __align__(16) unsigned char g_whi[32768];
__device__ __align__(16) unsigned char g_wlo[32768];
__device__ __align__(16) unsigned char g_lwhi[32768];
__device__ __align__(16) unsigned char g_lwlo[32768];

// ---------------- helpers ----------------
__device__ __forceinline__ uint32_t s2u(const void* p) {
    uint32_t a;
    asm("{ .reg .u64 t; cvta.to.shared.u64 t, %1; cvt.u32.u64 %0, t; }" : "=r"(a) : "l"(p));
    return a;
}

// swizzled byte offset inside a [rows][128 bf16] tile (256B rows, XOR-16B-chunk swizzle)
__device__ __forceinline__ uint32_t swz(int row, int col) {
    return (uint32_t)(row * 256 + ((((col >> 3) ^ (row & 7))) << 4) + (col & 7) * 2);
}

#define LDSM4(r, addr) \
    asm volatile("ldmatrix.sync.aligned.m8n8.x4.shared.b16 {%0,%1,%2,%3}, [%4];" \
        : "=r"((r)[0]), "=r"((r)[1]), "=r"((r)[2]), "=r"((r)[3]) : "r"(addr))

#define MMA16816(d, a, b0, b1) \
    asm volatile("mma.sync.aligned.m16n8k16.row.col.f32.bf16.bf16.f32 " \
        "{%0,%1,%2,%3}, {%4,%5,%6,%7}, {%8,%9}, {%0,%1,%2,%3};" \
        : "+f"((d)[0]), "+f"((d)[1]), "+f"((d)[2]), "+f"((d)[3]) \
        : "r"((a)[0]), "r"((a)[1]), "r"((a)[2]), "r"((a)[3]), "r"(b0), "r"(b1))

// ---------------- software grid barrier ----------------
__device__ __forceinline__ void gbar(int ph) {
    __syncthreads();
    if (threadIdx.x == 0) {
        __threadfence();
        atomicAdd(&g_c[ph], 1u);
        while (*(volatile unsigned*)&g_c[ph] < (unsigned)NBLK) { __nanosleep(64); }
        __threadfence();
    }
    __syncthreads();
}

// ---------------- fused CSR build ----------------
__global__ void __launch_bounds__(CBS, 1) csr_build(const int* __restrict__ ei, int E, int N)
{
    __shared__ int sm[CBS];
    const int b = blockIdx.x, t = threadIdx.x;
    const int gt = b * CBS + t;
    const int GS = NBLK * CBS;
    const int CHUNK = (N + NBLK - 1) / NBLK;
    const int base = b * CHUNK;

    for (int i = gt; i < N; i += GS) g_deg[i] = 0;
    gbar(0);

    for (int i = gt; i < E; i += GS) atomicAdd(&g_deg[ei[E + i]], 1);
    gbar(1);

    int myv = 0;
    if (t < CHUNK && base + t < N) myv = __ldcg(&g_deg[base + t]);
    sm[t] = myv;
    __syncthreads();
#pragma unroll
    for (int d = 1; d < CBS; d <<= 1) {
        int v2 = (t >= d) ? sm[t - d] : 0;
        __syncthreads();
        sm[t] += v2;
        __syncthreads();
    }
    int incl = sm[t];
    if (t < CHUNK && base + t < N) g_off[base + t] = incl - myv;
    if (t == CBS - 1) g_bsum[b] = incl;
    gbar(2);

    if (b == 0) {
        int v = (t < NBLK) ? __ldcg(&g_bsum[t]) : 0;
        sm[t] = v;
        __syncthreads();
#pragma unroll
        for (int d = 1; d < CBS; d <<= 1) {
            int v2 = (t >= d) ? sm[t - d] : 0;
            __syncthreads();
            sm[t] += v2;
            __syncthreads();
        }
        if (t < NBLK) g_bsum[t] = sm[t] - v;
    }
    gbar(3);

    {
        int boff = __ldcg(&g_bsum[b]);
        if (t < CHUNK && base + t < N) {
            int o = g_off[base + t] + boff;
            g_off[base + t] = o;
            g_cur[base + t] = o;
        }
    }
    gbar(4);

    for (int i = gt; i < E; i += GS) {
        int dst = ei[E + i];
        int pos = atomicAdd(&g_cur[dst], 1);
        g_srcs[pos] = ei[i];
    }
    gbar(5);

    if (b == 0 && t < 8) g_c[t] = 0;
}

// ---------------- prep: W^T and lin_w^T -> bf16 hi/lo, swizzled (one launch) ----------------
__global__ void prep_all(const float* __restrict__ W, const float* __restrict__ LW) {
    int idx = blockIdx.x * blockDim.x + threadIdx.x;   // 32768
    int m   = idx >> 14;
    int rem = idx & 16383;
    int n = rem >> 7, k = rem & 127;
    const float* src = m ? LW : W;
    unsigned char* dhi = m ? g_lwhi : g_whi;
    unsigned char* dlo = m ? g_lwlo : g_wlo;
    float v = src[k * CH + n];
    __nv_bfloat16 h = __float2bfloat16(v);
    __nv_bfloat16 l = __float2bfloat16(v - __bfloat162float(h));
    uint32_t o = swz(n, k);
    *reinterpret_cast<__nv_bfloat16*>(dhi + o) = h;
    *reinterpret_cast<__nv_bfloat16*>(dlo + o) = l;
}

// ---------------- gemm1: g_h = x @ W, fused a_src/a_dst epilogue ----------------
__global__ void __launch_bounds__(256, 2) gemm1_mma(
    const float* __restrict__ A,
    const unsigned char* __restrict__ Bhi_g, const unsigned char* __restrict__ Blo_g,
    const float* __restrict__ v0, const float* __restrict__ v1,
    float* __restrict__ C, int M)
{
    extern __shared__ __align__(16) unsigned char smem[];
    // layout: A_hi 16K | A_lo 16K | B_hi 32K | B_lo 32K
    const uint32_t sb = s2u(smem);
    const int tid = threadIdx.x, lane = tid & 31, w = tid >> 5;
    const int row0 = blockIdx.x * 64;

    {
        const int4* bh = reinterpret_cast<const int4*>(Bhi_g);
        const int4* bl = reinterpret_cast<const int4*>(Blo_g);
        int4* dh = reinterpret_cast<int4*>(smem + 32768);
        int4* dl = reinterpret_cast<int4*>(smem + 65536);
#pragma unroll
        for (int u = 0; u < 8; ++u) {
            int f = tid + u * 256;
            dh[f] = bh[f];
            dl[f] = bl[f];
        }
    }

#pragma unroll
    for (int u = 0; u < 8; ++u) {
        int f = tid + u * 256;
        int r = f >> 5;
        int c = (f & 31) * 4;
        float4 v = make_float4(0.f, 0.f, 0.f, 0.f);
        if (row0 + r < M)
            v = *reinterpret_cast<const float4*>(&A[(size_t)(row0 + r) * CH + c]);
        __nv_bfloat162 h01 = __floats2bfloat162_rn(v.x, v.y);
        __nv_bfloat162 h23 = __floats2bfloat162_rn(v.z, v.w);
        __nv_bfloat162 lo01 = __floats2bfloat162_rn(v.x - __bfloat162float(h01.x),
                                                    v.y - __bfloat162float(h01.y));
        __nv_bfloat162 lo23 = __floats2bfloat162_rn(v.z - __bfloat162float(h23.x),
                                                    v.w - __bfloat162float(h23.y));
        uint32_t o = swz(r, c);
        uint2 uh, ul;
        uh.x = *reinterpret_cast<uint32_t*>(&h01);
        uh.y = *reinterpret_cast<uint32_t*>(&h23);
        ul.x = *reinterpret_cast<uint32_t*>(&lo01);
        ul.y = *reinterpret_cast<uint32_t*>(&lo23);
        *reinterpret_cast<uint2*>(smem + o)         = uh;
        *reinterpret_cast<uint2*>(smem + 16384 + o) = ul;
    }
    __syncthreads();

    const int wr = (w >> 1) * 16;
    const int wc = (w & 1) * 64;

    float acc[8][4];
#pragma unroll
    for (int j = 0; j < 8; ++j)
#pragma unroll
        for (int q = 0; q < 4; ++q) acc[j][q] = 0.f;

    const int arow  = wr + (lane & 7) + ((lane >> 3) & 1) * 8;
    const int asel  = lane >> 4;
    const int arow7 = arow & 7;
    const int bg_row = (lane & 7) + ((lane >> 4) & 1) * 8;
    const int bsel   = (lane >> 3) & 1;

#pragma unroll
    for (int kk = 0; kk < 8; ++kk) {
        uint32_t a_hi[4], a_lo[4];
        uint32_t aaddr = sb + (uint32_t)(arow * 256) +
                         (uint32_t)((((kk * 2 + asel) ^ arow7)) << 4);
        LDSM4(a_hi, aaddr);
        LDSM4(a_lo, aaddr + 16384);

        uint32_t b_hi[16], b_lo[16];
#pragma unroll
        for (int g = 0; g < 4; ++g) {
            int brow = wc + g * 16 + bg_row;
            uint32_t baddr = sb + 32768 + (uint32_t)(brow * 256) +
                             (uint32_t)((((kk * 2 + bsel) ^ (brow & 7))) << 4);
            LDSM4(&b_hi[g * 4], baddr);
            LDSM4(&b_lo[g * 4], baddr + 32768);
        }

#pragma unroll
        for (int j = 0; j < 8; ++j) {
            int i0 = (j >> 1) * 4 + (j & 1) * 2;
            MMA16816(acc[j], a_hi, b_hi[i0], b_hi[i0 + 1]);
            MMA16816(acc[j], a_hi, b_lo[i0], b_lo[i0 + 1]);
            MMA16816(acc[j], a_lo, b_hi[i0], b_hi[i0 + 1]);
        }
    }

    const int r_g = row0 + wr + (lane >> 2);
#pragma unroll
    for (int j = 0; j < 8; ++j) {
        int n0 = wc + j * 8 + (lane & 3) * 2;
        float2 o0 = make_float2(acc[j][0], acc[j][1]);
        float2 o1 = make_float2(acc[j][2], acc[j][3]);
        if (r_g < M)
            *reinterpret_cast<float2*>(&C[(size_t)r_g * CH + n0]) = o0;
        if (r_g + 8 < M)
            *reinterpret_cast<float2*>(&C[(size_t)(r_g + 8) * CH + n0]) = o1;
    }

    // fused att projections: this warp covers heads (wc/32, wc/32+1)
    {
        float ps[2][2] = {{0.f, 0.f}, {0.f, 0.f}};
        float pd[2][2] = {{0.f, 0.f}, {0.f, 0.f}};
#pragma unroll
        for (int j = 0; j < 8; ++j) {
            int n0 = wc + j * 8 + (lane & 3) * 2;
            float s0 = __ldg(&v0[n0]), s1 = __ldg(&v0[n0 + 1]);
            float d0 = __ldg(&v1[n0]), d1 = __ldg(&v1[n0 + 1]);
            int hh = j >> 2;
            ps[hh][0] += acc[j][0] * s0 + acc[j][1] * s1;
            ps[hh][1] += acc[j][2] * s0 + acc[j][3] * s1;
            pd[hh][0] += acc[j][0] * d0 + acc[j][1] * d1;
            pd[hh][1] += acc[j][2] * d0 + acc[j][3] * d1;
        }
#pragma unroll
        for (int o = 1; o < 4; o <<= 1) {
#pragma unroll
            for (int hh = 0; hh < 2; ++hh)
#pragma unroll
                for (int rh = 0; rh < 2; ++rh) {
                    ps[hh][rh] += __shfl_xor_sync(0xFFFFFFFFu, ps[hh][rh], o);
                    pd[hh][rh] += __shfl_xor_sync(0xFFFFFFFFu, pd[hh][rh], o);
                }
        }
        if ((lane & 3) == 0) {
            int h0 = wc >> 5;
            if (r_g < M) {
                g_asrc[(size_t)r_g * HEADS + h0]     = ps[0][0];
                g_asrc[(size_t)r_g * HEADS + h0 + 1] = ps[1][0];
                g_adst[(size_t)r_g * HEADS + h0]     = pd[0][0];
                g_adst[(size_t)r_g * HEADS + h0 + 1] = pd[1][0];
            }
            if (r_g + 8 < M) {
                g_asrc[(size_t)(r_g + 8) * HEADS + h0]     = ps[0][1];
                g_asrc[(size_t)(r_g + 8) * HEADS + h0 + 1] = ps[1][1];
                g_adst[(size_t)(r_g + 8) * HEADS + h0]     = pd[0][1];
                g_adst[(size_t)(r_g + 8) * HEADS + h0 + 1] = pd[1][1];
            }
        }
    }
}

// ---------------- fused gather + gemm2: out = relu((gathered msgs) @ lin_w + b) ----------------
// block: 256 thr, 64-node tile. Phase 1: warp w gathers nodes [w*8, w*8+8),
// normalizes in registers, splits to bf16 hi/lo DIRECTLY into the MMA A-tile.
// Phase 2: identical MMA as gemm1, epilogue bias+ReLU to out.
__global__ void __launch_bounds__(256, 2) gather_gemm(
    const unsigned char* __restrict__ Bhi_g, const unsigned char* __restrict__ Blo_g,
    const float* __restrict__ bias, float* __restrict__ out, int N)
{
    extern __shared__ __align__(16) unsigned char smem[];
    const uint32_t sb = s2u(smem);
    const int tid = threadIdx.x, lane = tid & 31, w = tid >> 5;
    const int row0 = blockIdx.x * 64;
    const int head = lane >> 3;

    // B tiles (lin_w images)
    {
        const int4* bh = reinterpret_cast<const int4*>(Bhi_g);
        const int4* bl = reinterpret_cast<const int4*>(Blo_g);
        int4* dh = reinterpret_cast<int4*>(smem + 32768);
        int4* dl = reinterpret_cast<int4*>(smem + 65536);
#pragma unroll
        for (int u = 0; u < 8; ++u) {
            int f = tid + u * 256;
            dh[f] = bh[f];
            dl[f] = bl[f];
        }
    }

    // Phase 1: gather 8 nodes per warp
    for (int i = 0; i < 8; ++i) {
        const int r_local = w * 8 + i;
        const int node = row0 + r_local;

        float a0 = 0.f, a1 = 0.f, a2 = 0.f, a3 = 0.f;
        float s_my = 0.f;

        if (node < N) {
            int off = g_off[node];
            int deg = g_deg[node];

            float4 ad4 = *reinterpret_cast<const float4*>(&g_adst[(size_t)node * HEADS]);
            float ad_my = (lane & 16) ? ((lane & 8) ? ad4.w : ad4.z)
                                      : ((lane & 8) ? ad4.y : ad4.x);

            for (int base = 0; base < deg; base += 32) {
                int idx = 0;
                if (base + lane < deg) idx = g_srcs[off + base + lane];
                int cnt = min(32, deg - base);
                int j = 0;
                for (; j + 4 <= cnt; j += 4) {
                    int s0 = __shfl_sync(0xFFFFFFFFu, idx, j);
                    int s1 = __shfl_sync(0xFFFFFFFFu, idx, j + 1);
                    int s2 = __shfl_sync(0xFFFFFFFFu, idx, j + 2);
                    int s3 = __shfl_sync(0xFFFFFFFFu, idx, j + 3);
                    float as0 = __ldg(&g_asrc[(size_t)s0 * HEADS + head]);
                    float as1 = __ldg(&g_asrc[(size_t)s1 * HEADS + head]);
                    float as2 = __ldg(&g_asrc[(size_t)s2 * HEADS + head]);
                    float as3 = __ldg(&g_asrc[(size_t)s3 * HEADS + head]);
                    float4 h0 = *reinterpret_cast<const float4*>(&g_h[(size_t)s0 * CH + lane * 4]);
                    float4 h1 = *reinterpret_cast<const float4*>(&g_h[(size_t)s1 * CH + lane * 4]);
                    float4 h2 = *reinterpret_cast<const float4*>(&g_h[(size_t)s2 * CH + lane * 4]);
                    float4 h3 = *reinterpret_cast<const float4*>(&g_h[(size_t)s3 * CH + lane * 4]);

                    float e0 = as0 + ad_my; e0 = (e0 > 0.f) ? e0 : NEG_SLOPE * e0;
                    float e1 = as1 + ad_my; e1 = (e1 > 0.f) ? e1 : NEG_SLOPE * e1;
                    float e2 = as2 + ad_my; e2 = (e2 > 0.f) ? e2 : NEG_SLOPE * e2;
                    float e3 = as3 + ad_my; e3 = (e3 > 0.f) ? e3 : NEG_SLOPE * e3;
                    float x0 = __expf(e0), x1 = __expf(e1), x2 = __expf(e2), x3 = __expf(e3);

                    a0 = fmaf(x0, h0.x, a0); a1 = fmaf(x0, h0.y, a1);
                    a2 = fmaf(x0, h0.z, a2); a3 = fmaf(x0, h0.w, a3);
                    a0 = fmaf(x1, h1.x, a0); a1 = fmaf(x1, h1.y, a1);
                    a2 = fmaf(x1, h1.z, a2); a3 = fmaf(x1, h1.w, a3);
                    a0 = fmaf(x2, h2.x, a0); a1 = fmaf(x2, h2.y, a1);
                    a2 = fmaf(x2, h2.z, a2); a3 = fmaf(x2, h2.w, a3);
                    a0 = fmaf(x3, h3.x, a0); a1 = fmaf(x3, h3.y, a1);
                    a2 = fmaf(x3, h3.z, a2); a3 = fmaf(x3, h3.w, a3);
                    s_my += x0 + x1 + x2 + x3;
                }
                for (; j < cnt; ++j) {
                    int src = __shfl_sync(0xFFFFFFFFu, idx, j);
                    float as_my = __ldg(&g_asrc[(size_t)src * HEADS + head]);
                    float eh = as_my + ad_my;
                    eh = (eh > 0.f) ? eh : NEG_SLOPE * eh;
                    float ex = __expf(eh);
                    float4 hv = *reinterpret_cast<const float4*>(&g_h[(size_t)src * CH + lane * 4]);
                    a0 = fmaf(ex, hv.x, a0);
                    a1 = fmaf(ex, hv.y, a1);
                    a2 = fmaf(ex, hv.z, a2);
                    a3 = fmaf(ex, hv.w, a3);
                    s_my += ex;
                }
            }
        }

        float inv = 1.f / (s_my + 1e-16f);
        float o0 = a0 * inv, o1 = a1 * inv, o2 = a2 * inv, o3 = a3 * inv;

        // split fp32 -> bf16 hi/lo and store into MMA A-tile
        __nv_bfloat162 h01 = __floats2bfloat162_rn(o0, o1);
        __nv_bfloat162 h23 = __floats2bfloat162_rn(o2, o3);
        __nv_bfloat162 lo01 = __floats2bfloat162_rn(o0 - __bfloat162float(h01.x),
                                                    o1 - __bfloat162float(h01.y));
        __nv_bfloat162 lo23 = __floats2bfloat162_rn(o2 - __bfloat162float(h23.x),
                                                    o3 - __bfloat162float(h23.y));
        uint32_t o = swz(r_local, lane * 4);
        uint2 uh, ul;
        uh.x = *reinterpret_cast<uint32_t*>(&h01);
        uh.y = *reinterpret_cast<uint32_t*>(&h23);
        ul.x = *reinterpret_cast<uint32_t*>(&lo01);
        ul.y = *reinterpret_cast<uint32_t*>(&lo23);
        *reinterpret_cast<uint2*>(smem + o)         = uh;
        *reinterpret_cast<uint2*>(smem + 16384 + o) = ul;
    }
    __syncthreads();

    // Phase 2: MMA (identical shape to gemm1), epilogue bias + ReLU
    const int wr = (w >> 1) * 16;
    const int wc = (w & 1) * 64;

    float acc[8][4];
#pragma unroll
    for (int j = 0; j < 8; ++j)
#pragma unroll
        for (int q = 0; q < 4; ++q) acc[j][q] = 0.f;

    const int arow  = wr + (lane & 7) + ((lane >> 3) & 1) * 8;
    const int asel  = lane >> 4;
    const int arow7 = arow & 7;
    const int bg_row = (lane & 7) + ((lane >> 4) & 1) * 8;
    const int bsel   = (lane >> 3) & 1;

#pragma unroll
    for (int kk = 0; kk < 8; ++kk) {
        uint32_t a_hi[4], a_lo[4];
        uint32_t aaddr = sb + (uint32_t)(arow * 256) +
                         (uint32_t)((((kk * 2 + asel) ^ arow7)) << 4);
        LDSM4(a_hi, aaddr);
        LDSM4(a_lo, aaddr + 16384);

        uint32_t b_hi[16], b_lo[16];
#pragma unroll
        for (int g = 0; g < 4; ++g) {
            int brow = wc + g * 16 + bg_row;
            uint32_t baddr = sb + 32768 + (uint32_t)(brow * 256) +
                             (uint32_t)((((kk * 2 + bsel) ^ (brow & 7))) << 4);
            LDSM4(&b_hi[g * 4], baddr);
            LDSM4(&b_lo[g * 4], baddr + 32768);
        }

#pragma unroll
        for (int j = 0; j < 8; ++j) {
            int i0 = (j >> 1) * 4 + (j & 1) * 2;
            MMA16816(acc[j], a_hi, b_hi[i0], b_hi[i0 + 1]);
            MMA16816(acc[j], a_hi, b_lo[i0], b_lo[i0 + 1]);
            MMA16816(acc[j], a_lo, b_hi[i0], b_hi[i0 + 1]);
        }
    }

    const int r_g = row0 + wr + (lane >> 2);
#pragma unroll
    for (int j = 0; j < 8; ++j) {
        int n0 = wc + j * 8 + (lane & 3) * 2;
        float b0 = __ldg(&bias[n0]), b1 = __ldg(&bias[n0 + 1]);
        float2 o0, o1;
        o0.x = fmaxf(acc[j][0] + b0, 0.f);
        o0.y = fmaxf(acc[j][1] + b1, 0.f);
        o1.x = fmaxf(acc[j][2] + b0, 0.f);
        o1.y = fmaxf(acc[j][3] + b1, 0.f);
        if (r_g < N)
            *reinterpret_cast<float2*>(&out[(size_t)r_g * CH + n0]) = o0;
        if (r_g + 8 < N)
            *reinterpret_cast<float2*>(&out[(size_t)(r_g + 8) * CH + n0]) = o1;
    }
}

// ---------------- launch ----------------
extern "C" void kernel_launch(void* const* d_in, const int* in_sizes, int n_in,
                              void* d_out, int out_size)
{
    const float* x     = (const float*)d_in[0];
    const int*   ei    = (const int*)  d_in[1];
    const float* W     = (const float*)d_in[2];
    const float* att_s = (const float*)d_in[3];
    const float* att_d = (const float*)d_in[4];
    const float* lin_w = (const float*)d_in[5];
    const float* lin_b = (const float*)d_in[6];
    float* out = (float*)d_out;

    int N = in_sizes[0] / CH;    // 100000
    int E = in_sizes[1] / 2;     // 1600000

    void *p_h, *p_whi, *p_wlo, *p_lwhi, *p_lwlo;
    cudaGetSymbolAddress(&p_h, g_h);
    cudaGetSymbolAddress(&p_whi, g_whi);
    cudaGetSymbolAddress(&p_wlo, g_wlo);
    cudaGetSymbolAddress(&p_lwhi, g_lwhi);
    cudaGetSymbolAddress(&p_lwlo, g_lwlo);

    const int SMEM = 98304;
    cudaFuncSetAttribute(gemm1_mma,   cudaFuncAttributeMaxDynamicSharedMemorySize, SMEM);
    cudaFuncSetAttribute(gather_gemm, cudaFuncAttributeMaxDynamicSharedMemorySize, SMEM);

    int gemm_blocks = (N + 63) / 64;

    cudaStream_t s2;
    cudaStreamCreateWithFlags(&s2, cudaStreamNonBlocking);
    cudaEvent_t ev_fork, ev_join;
    cudaEventCreateWithFlags(&ev_fork, cudaEventDisableTiming);
    cudaEventCreateWithFlags(&ev_join, cudaEventDisableTiming);

    cudaEventRecord(ev_fork, 0);
    cudaStreamWaitEvent(s2, ev_fork, 0);

    prep_all<<<128, 256>>>(W, lin_w);                                           // 0
    gemm1_mma<<<gemm_blocks, 256, SMEM>>>(                                      // 1
        x, (const unsigned char*)p_whi, (const unsigned char*)p_wlo,
        att_s, att_d, (float*)p_h, N);

    csr_build<<<NBLK, CBS, 0, s2>>>(ei, E, N);                                  // 2 (s2, concurrent)
    cudaEventRecord(ev_join, s2);
    cudaStreamWaitEvent(0, ev_join, 0);

    gather_gemm<<<gemm_blocks, 256, SMEM>>>(                                    // 3 <- profiled
        (const unsigned char*)p_lwhi, (const unsigned char*)p_lwlo,
        lin_b, out, N);
}

// round 9
// speedup vs baseline: 1.2526x; 1.2526x over previous
#include <cuda_runtime.h>
#include <cuda_bf16.h>
#include <cuda_fp16.h>
#include <cstdint>

#define N_NODES 100000
#define N_EDGES 1600000
#define CH 128          // IN_CH = HEADS*HID = OUT_CH = 128
#define HEADS 4
#define HID 32
#define NEG_SLOPE 0.2f
#define NBLK 148
#define CBS 1024

// ---------------- scratch (static device globals; no allocation) ----------------
__device__ __half g_h[(size_t)N_NODES * CH];      // x @ W, fp16 (25.6 MB)
__device__ float g_accum[(size_t)N_NODES * CH];   // normalized messages (51.2 MB)
__device__ float g_asrc[(size_t)N_NODES * HEADS];
__device__ float g_adst[(size_t)N_NODES * HEADS];
__device__ int   g_deg[N_NODES];
__device__ int   g_off[N_NODES];
__device__ int   g_cur[N_NODES];
__device__ int   g_srcs[N_EDGES];
__device__ int   g_bsum[NBLK];
__device__ unsigned g_c[8];                        // grid-barrier counters (zero-init)
// pre-swizzled bf16 hi/lo images of W^T and lin_w^T ([n][k] layout, 32KB each)
__device__ __align__(16) unsigned char g_whi[32768];
__device__ __align__(16) unsigned char g_wlo[32768];
__device__ __align__(16) unsigned char g_lwhi[32768];
__device__ __align__(16) unsigned char g_lwlo[32768];

// ---------------- helpers ----------------
__device__ __forceinline__ uint32_t s2u(const void* p) {
    uint32_t a;
    asm("{ .reg .u64 t; cvta.to.shared.u64 t, %1; cvt.u32.u64 %0, t; }" : "=r"(a) : "l"(p));
    return a;
}

// swizzled byte offset inside a [rows][128 bf16] tile (256B rows, XOR-16B-chunk swizzle)
__device__ __forceinline__ uint32_t swz(int row, int col) {
    return (uint32_t)(row * 256 + ((((col >> 3) ^ (row & 7))) << 4) + (col & 7) * 2);
}

#define LDSM4(r, addr) \
    asm volatile("ldmatrix.sync.aligned.m8n8.x4.shared.b16 {%0,%1,%2,%3}, [%4];" \
        : "=r"((r)[0]), "=r"((r)[1]), "=r"((r)[2]), "=r"((r)[3]) : "r"(addr))

#define MMA16816(d, a, b0, b1) \
    asm volatile("mma.sync.aligned.m16n8k16.row.col.f32.bf16.bf16.f32 " \
        "{%0,%1,%2,%3}, {%4,%5,%6,%7}, {%8,%9}, {%0,%1,%2,%3};" \
        : "+f"((d)[0]), "+f"((d)[1]), "+f"((d)[2]), "+f"((d)[3]) \
        : "r"((a)[0]), "r"((a)[1]), "r"((a)[2]), "r"((a)[3]), "r"(b0), "r"(b1))

// ---------------- software grid barrier ----------------
__device__ __forceinline__ void gbar(int ph) {
    __syncthreads();
    if (threadIdx.x == 0) {
        __threadfence();
        atomicAdd(&g_c[ph], 1u);
        while (*(volatile unsigned*)&g_c[ph] < (unsigned)NBLK) { __nanosleep(64); }
        __threadfence();
    }
    __syncthreads();
}

// ---------------- fused CSR build ----------------
__global__ void __launch_bounds__(CBS, 1) csr_build(const int* __restrict__ ei, int E, int N)
{
    __shared__ int sm[CBS];
    const int b = blockIdx.x, t = threadIdx.x;
    const int gt = b * CBS + t;
    const int GS = NBLK * CBS;
    const int CHUNK = (N + NBLK - 1) / NBLK;
    const int base = b * CHUNK;

    for (int i = gt; i < N; i += GS) g_deg[i] = 0;
    gbar(0);

    for (int i = gt; i < E; i += GS) atomicAdd(&g_deg[ei[E + i]], 1);
    gbar(1);

    int myv = 0;
    if (t < CHUNK && base + t < N) myv = __ldcg(&g_deg[base + t]);
    sm[t] = myv;
    __syncthreads();
#pragma unroll
    for (int d = 1; d < CBS; d <<= 1) {
        int v2 = (t >= d) ? sm[t - d] : 0;
        __syncthreads();
        sm[t] += v2;
        __syncthreads();
    }
    int incl = sm[t];
    if (t < CHUNK && base + t < N) g_off[base + t] = incl - myv;
    if (t == CBS - 1) g_bsum[b] = incl;
    gbar(2);

    if (b == 0) {
        int v = (t < NBLK) ? __ldcg(&g_bsum[t]) : 0;
        sm[t] = v;
        __syncthreads();
#pragma unroll
        for (int d = 1; d < CBS; d <<= 1) {
            int v2 = (t >= d) ? sm[t - d] : 0;
            __syncthreads();
            sm[t] += v2;
            __syncthreads();
        }
        if (t < NBLK) g_bsum[t] = sm[t] - v;
    }
    gbar(3);

    {
        int boff = __ldcg(&g_bsum[b]);
        if (t < CHUNK && base + t < N) {
            int o = g_off[base + t] + boff;
            g_off[base + t] = o;
            g_cur[base + t] = o;
        }
    }
    gbar(4);

    for (int i = gt; i < E; i += GS) {
        int dst = ei[E + i];
        int pos = atomicAdd(&g_cur[dst], 1);
        g_srcs[pos] = ei[i];
    }
    gbar(5);

    if (b == 0 && t < 8) g_c[t] = 0;
}

// ---------------- prep: W^T and lin_w^T -> bf16 hi/lo, swizzled (one launch) ----------------
__global__ void prep_all(const float* __restrict__ W, const float* __restrict__ LW) {
    int idx = blockIdx.x * blockDim.x + threadIdx.x;   // 32768
    int m   = idx >> 14;
    int rem = idx & 16383;
    int n = rem >> 7, k = rem & 127;
    const float* src = m ? LW : W;
    unsigned char* dhi = m ? g_lwhi : g_whi;
    unsigned char* dlo = m ? g_lwlo : g_wlo;
    float v = src[k * CH + n];
    __nv_bfloat16 h = __float2bfloat16(v);
    __nv_bfloat16 l = __float2bfloat16(v - __bfloat162float(h));
    uint32_t o = swz(n, k);
    *reinterpret_cast<__nv_bfloat16*>(dhi + o) = h;
    *reinterpret_cast<__nv_bfloat16*>(dlo + o) = l;
}

// ---------------- tensor-core GEMM (split-bf16 3-product) ----------------
// MODE 0: gemm1 -> C = g_h (fp16) + fused a_src/a_dst epilogue (v0=att_s, v1=att_d)
// MODE 1: gemm2 -> C = out (fp32) with bias(v0) + ReLU
template<int MODE>
__global__ void __launch_bounds__(256, 2) gemm_mma(
    const float* __restrict__ A,
    const unsigned char* __restrict__ Bhi_g, const unsigned char* __restrict__ Blo_g,
    const float* __restrict__ v0, const float* __restrict__ v1,
    void* __restrict__ Cv, int M)
{
    extern __shared__ __align__(16) unsigned char smem[];
    // layout: A_hi 16K | A_lo 16K | B_hi 32K | B_lo 32K
    const uint32_t sb = s2u(smem);
    const int tid = threadIdx.x, lane = tid & 31, w = tid >> 5;
    const int row0 = blockIdx.x * 64;

    {
        const int4* bh = reinterpret_cast<const int4*>(Bhi_g);
        const int4* bl = reinterpret_cast<const int4*>(Blo_g);
        int4* dh = reinterpret_cast<int4*>(smem + 32768);
        int4* dl = reinterpret_cast<int4*>(smem + 65536);
#pragma unroll
        for (int u = 0; u < 8; ++u) {
            int f = tid + u * 256;
            dh[f] = bh[f];
            dl[f] = bl[f];
        }
    }

#pragma unroll
    for (int u = 0; u < 8; ++u) {
        int f = tid + u * 256;
        int r = f >> 5;
        int c = (f & 31) * 4;
        float4 v = make_float4(0.f, 0.f, 0.f, 0.f);
        if (row0 + r < M)
            v = *reinterpret_cast<const float4*>(&A[(size_t)(row0 + r) * CH + c]);
        __nv_bfloat162 h01 = __floats2bfloat162_rn(v.x, v.y);
        __nv_bfloat162 h23 = __floats2bfloat162_rn(v.z, v.w);
        __nv_bfloat162 lo01 = __floats2bfloat162_rn(v.x - __bfloat162float(h01.x),
                                                    v.y - __bfloat162float(h01.y));
        __nv_bfloat162 lo23 = __floats2bfloat162_rn(v.z - __bfloat162float(h23.x),
                                                    v.w - __bfloat162float(h23.y));
        uint32_t o = swz(r, c);
        uint2 uh, ul;
        uh.x = *reinterpret_cast<uint32_t*>(&h01);
        uh.y = *reinterpret_cast<uint32_t*>(&h23);
        ul.x = *reinterpret_cast<uint32_t*>(&lo01);
        ul.y = *reinterpret_cast<uint32_t*>(&lo23);
        *reinterpret_cast<uint2*>(smem + o)         = uh;
        *reinterpret_cast<uint2*>(smem + 16384 + o) = ul;
    }
    __syncthreads();

    const int wr = (w >> 1) * 16;
    const int wc = (w & 1) * 64;

    float acc[8][4];
#pragma unroll
    for (int j = 0; j < 8; ++j)
#pragma unroll
        for (int q = 0; q < 4; ++q) acc[j][q] = 0.f;

    const int arow  = wr + (lane & 7) + ((lane >> 3) & 1) * 8;
    const int asel  = lane >> 4;
    const int arow7 = arow & 7;
    const int bg_row = (lane & 7) + ((lane >> 4) & 1) * 8;
    const int bsel   = (lane >> 3) & 1;

#pragma unroll
    for (int kk = 0; kk < 8; ++kk) {
        uint32_t a_hi[4], a_lo[4];
        uint32_t aaddr = sb + (uint32_t)(arow * 256) +
                         (uint32_t)((((kk * 2 + asel) ^ arow7)) << 4);
        LDSM4(a_hi, aaddr);
        LDSM4(a_lo, aaddr + 16384);

        uint32_t b_hi[16], b_lo[16];
#pragma unroll
        for (int g = 0; g < 4; ++g) {
            int brow = wc + g * 16 + bg_row;
            uint32_t baddr = sb + 32768 + (uint32_t)(brow * 256) +
                             (uint32_t)((((kk * 2 + bsel) ^ (brow & 7))) << 4);
            LDSM4(&b_hi[g * 4], baddr);
            LDSM4(&b_lo[g * 4], baddr + 32768);
        }

#pragma unroll
        for (int j = 0; j < 8; ++j) {
            int i0 = (j >> 1) * 4 + (j & 1) * 2;
            MMA16816(acc[j], a_hi, b_hi[i0], b_hi[i0 + 1]);
            MMA16816(acc[j], a_hi, b_lo[i0], b_lo[i0 + 1]);
            MMA16816(acc[j], a_lo, b_hi[i0], b_hi[i0 + 1]);
        }
    }

    const int r_g = row0 + wr + (lane >> 2);
#pragma unroll
    for (int j = 0; j < 8; ++j) {
        int n0 = wc + j * 8 + (lane & 3) * 2;
        if (MODE == 1) {
            float* C = (float*)Cv;
            float b0 = __ldg(&v0[n0]), b1 = __ldg(&v0[n0 + 1]);
            float2 o0, o1;
            o0.x = fmaxf(acc[j][0] + b0, 0.f); o0.y = fmaxf(acc[j][1] + b1, 0.f);
            o1.x = fmaxf(acc[j][2] + b0, 0.f); o1.y = fmaxf(acc[j][3] + b1, 0.f);
            if (r_g < M)
                *reinterpret_cast<float2*>(&C[(size_t)r_g * CH + n0]) = o0;
            if (r_g + 8 < M)
                *reinterpret_cast<float2*>(&C[(size_t)(r_g + 8) * CH + n0]) = o1;
        } else {
            __half* C = (__half*)Cv;
            __half2 o0 = __float22half2_rn(make_float2(acc[j][0], acc[j][1]));
            __half2 o1 = __float22half2_rn(make_float2(acc[j][2], acc[j][3]));
            if (r_g < M)
                *reinterpret_cast<__half2*>(&C[(size_t)r_g * CH + n0]) = o0;
            if (r_g + 8 < M)
                *reinterpret_cast<__half2*>(&C[(size_t)(r_g + 8) * CH + n0]) = o1;
        }
    }

    if (MODE == 0) {
        // fused att projections: this warp covers heads (wc/32, wc/32+1)
        float ps[2][2] = {{0.f, 0.f}, {0.f, 0.f}};
        float pd[2][2] = {{0.f, 0.f}, {0.f, 0.f}};
#pragma unroll
        for (int j = 0; j < 8; ++j) {
            int n0 = wc + j * 8 + (lane & 3) * 2;
            float s0 = __ldg(&v0[n0]), s1 = __ldg(&v0[n0 + 1]);
            float d0 = __ldg(&v1[n0]), d1 = __ldg(&v1[n0 + 1]);
            int hh = j >> 2;
            ps[hh][0] += acc[j][0] * s0 + acc[j][1] * s1;
            ps[hh][1] += acc[j][2] * s0 + acc[j][3] * s1;
            pd[hh][0] += acc[j][0] * d0 + acc[j][1] * d1;
            pd[hh][1] += acc[j][2] * d0 + acc[j][3] * d1;
        }
#pragma unroll
        for (int o = 1; o < 4; o <<= 1) {
#pragma unroll
            for (int hh = 0; hh < 2; ++hh)
#pragma unroll
                for (int rh = 0; rh < 2; ++rh) {
                    ps[hh][rh] += __shfl_xor_sync(0xFFFFFFFFu, ps[hh][rh], o);
                    pd[hh][rh] += __shfl_xor_sync(0xFFFFFFFFu, pd[hh][rh], o);
                }
        }
        if ((lane & 3) == 0) {
            int h0 = wc >> 5;
            if (r_g < M) {
                g_asrc[(size_t)r_g * HEADS + h0]     = ps[0][0];
                g_asrc[(size_t)r_g * HEADS + h0 + 1] = ps[1][0];
                g_adst[(size_t)r_g * HEADS + h0]     = pd[0][0];
                g_adst[(size_t)r_g * HEADS + h0 + 1] = pd[1][0];
            }
            if (r_g + 8 < M) {
                g_asrc[(size_t)(r_g + 8) * HEADS + h0]     = ps[0][1];
                g_asrc[(size_t)(r_g + 8) * HEADS + h0 + 1] = ps[1][1];
                g_adst[(size_t)(r_g + 8) * HEADS + h0]     = pd[0][1];
                g_adst[(size_t)(r_g + 8) * HEADS + h0 + 1] = pd[1][1];
            }
        }
    }
}

// ---------------- gather: one warp per dst node, 4 edges in flight, fp16 h ----------------
__device__ __forceinline__ void h4_to_f(uint2 u, float& f0, float& f1, float& f2, float& f3) {
    float2 a = __half22float2(*reinterpret_cast<__half2*>(&u.x));
    float2 b = __half22float2(*reinterpret_cast<__half2*>(&u.y));
    f0 = a.x; f1 = a.y; f2 = b.x; f3 = b.y;
}

__global__ void __launch_bounds__(256) gather_kernel(int N)
{
    int node = (blockIdx.x * blockDim.x + threadIdx.x) >> 5;
    if (node >= N) return;
    int lane = threadIdx.x & 31;
    int head = lane >> 3;

    int off = g_off[node];
    int deg = g_deg[node];

    float4 ad4 = *reinterpret_cast<const float4*>(&g_adst[(size_t)node * HEADS]);
    float ad_my = (lane & 16) ? ((lane & 8) ? ad4.w : ad4.z)
                              : ((lane & 8) ? ad4.y : ad4.x);

    float a0 = 0.f, a1 = 0.f, a2 = 0.f, a3 = 0.f;
    float s_my = 0.f;

    for (int base = 0; base < deg; base += 32) {
        int idx = 0;
        if (base + lane < deg) idx = g_srcs[off + base + lane];
        int cnt = min(32, deg - base);
        int j = 0;
        for (; j + 4 <= cnt; j += 4) {
            int s0 = __shfl_sync(0xFFFFFFFFu, idx, j);
            int s1 = __shfl_sync(0xFFFFFFFFu, idx, j + 1);
            int s2 = __shfl_sync(0xFFFFFFFFu, idx, j + 2);
            int s3 = __shfl_sync(0xFFFFFFFFu, idx, j + 3);
            float as0 = __ldg(&g_asrc[(size_t)s0 * HEADS + head]);
            float as1 = __ldg(&g_asrc[(size_t)s1 * HEADS + head]);
            float as2 = __ldg(&g_asrc[(size_t)s2 * HEADS + head]);
            float as3 = __ldg(&g_asrc[(size_t)s3 * HEADS + head]);
            uint2 u0 = *reinterpret_cast<const uint2*>(&g_h[(size_t)s0 * CH + lane * 4]);
            uint2 u1 = *reinterpret_cast<const uint2*>(&g_h[(size_t)s1 * CH + lane * 4]);
            uint2 u2 = *reinterpret_cast<const uint2*>(&g_h[(size_t)s2 * CH + lane * 4]);
            uint2 u3 = *reinterpret_cast<const uint2*>(&g_h[(size_t)s3 * CH + lane * 4]);

            float e0 = as0 + ad_my; e0 = (e0 > 0.f) ? e0 : NEG_SLOPE * e0;
            float e1 = as1 + ad_my; e1 = (e1 > 0.f) ? e1 : NEG_SLOPE * e1;
            float e2 = as2 + ad_my; e2 = (e2 > 0.f) ? e2 : NEG_SLOPE * e2;
            float e3 = as3 + ad_my; e3 = (e3 > 0.f) ? e3 : NEG_SLOPE * e3;
            float x0 = __expf(e0), x1 = __expf(e1), x2 = __expf(e2), x3 = __expf(e3);

            float h0, h1, h2, h3;
            h4_to_f(u0, h0, h1, h2, h3);
            a0 = fmaf(x0, h0, a0); a1 = fmaf(x0, h1, a1);
            a2 = fmaf(x0, h2, a2); a3 = fmaf(x0, h3, a3);
            h4_to_f(u1, h0, h1, h2, h3);
            a0 = fmaf(x1, h0, a0); a1 = fmaf(x1, h1, a1);
            a2 = fmaf(x1, h2, a2); a3 = fmaf(x1, h3, a3);
            h4_to_f(u2, h0, h1, h2, h3);
            a0 = fmaf(x2, h0, a0); a1 = fmaf(x2, h1, a1);
            a2 = fmaf(x2, h2, a2); a3 = fmaf(x2, h3, a3);
            h4_to_f(u3, h0, h1, h2, h3);
            a0 = fmaf(x3, h0, a0); a1 = fmaf(x3, h1, a1);
            a2 = fmaf(x3, h2, a2); a3 = fmaf(x3, h3, a3);
            s_my += x0 + x1 + x2 + x3;
        }
        for (; j < cnt; ++j) {
            int src = __shfl_sync(0xFFFFFFFFu, idx, j);
            float as_my = __ldg(&g_asrc[(size_t)src * HEADS + head]);
            float eh = as_my + ad_my;
            eh = (eh > 0.f) ? eh : NEG_SLOPE * eh;
            float ex = __expf(eh);
            uint2 u = *reinterpret_cast<const uint2*>(&g_h[(size_t)src * CH + lane * 4]);
            float h0, h1, h2, h3;
            h4_to_f(u, h0, h1, h2, h3);
            a0 = fmaf(ex, h0, a0);
            a1 = fmaf(ex, h1, a1);
            a2 = fmaf(ex, h2, a2);
            a3 = fmaf(ex, h3, a3);
            s_my += ex;
        }
    }

    float inv = 1.f / (s_my + 1e-16f);
    float4 o = make_float4(a0 * inv, a1 * inv, a2 * inv, a3 * inv);
    *reinterpret_cast<float4*>(&g_accum[(size_t)node * CH + lane * 4]) = o;
}

// ---------------- launch ----------------
extern "C" void kernel_launch(void* const* d_in, const int* in_sizes, int n_in,
                              void* d_out, int out_size)
{
    const float* x     = (const float*)d_in[0];
    const int*   ei    = (const int*)  d_in[1];
    const float* W     = (const float*)d_in[2];
    const float* att_s = (const float*)d_in[3];
    const float* att_d = (const float*)d_in[4];
    const float* lin_w = (const float*)d_in[5];
    const float* lin_b = (const float*)d_in[6];
    float* out = (float*)d_out;

    int N = in_sizes[0] / CH;    // 100000
    int E = in_sizes[1] / 2;     // 1600000

    void *p_h, *p_acc, *p_whi, *p_wlo, *p_lwhi, *p_lwlo;
    cudaGetSymbolAddress(&p_h, g_h);
    cudaGetSymbolAddress(&p_acc, g_accum);
    cudaGetSymbolAddress(&p_whi, g_whi);
    cudaGetSymbolAddress(&p_wlo, g_wlo);
    cudaGetSymbolAddress(&p_lwhi, g_lwhi);
    cudaGetSymbolAddress(&p_lwlo, g_lwlo);

    const int SMEM = 98304;
    cudaFuncSetAttribute(gemm_mma<0>, cudaFuncAttributeMaxDynamicSharedMemorySize, SMEM);
    cudaFuncSetAttribute(gemm_mma<1>, cudaFuncAttributeMaxDynamicSharedMemorySize, SMEM);

    int gemm_blocks = (N + 63) / 64;

    // fork: csr_build (side stream) || prep + gemm1 (main stream) — R6-proven topology
    cudaStream_t s2;
    cudaStreamCreateWithFlags(&s2, cudaStreamNonBlocking);
    cudaEvent_t ev_fork, ev_join;
    cudaEventCreateWithFlags(&ev_fork, cudaEventDisableTiming);
    cudaEventCreateWithFlags(&ev_join, cudaEventDisableTiming);

    cudaEventRecord(ev_fork, 0);
    cudaStreamWaitEvent(s2, ev_fork, 0);
    csr_build<<<NBLK, CBS, 0, s2>>>(ei, E, N);                                  // 0
    cudaEventRecord(ev_join, s2);

    prep_all<<<128, 256>>>(W, lin_w);                                           // 1
    gemm_mma<0><<<gemm_blocks, 256, SMEM>>>(                                    // 2
        x, (const unsigned char*)p_whi, (const unsigned char*)p_wlo,
        att_s, att_d, p_h, N);

    cudaStreamWaitEvent(0, ev_join, 0);
    gather_kernel<<<(N * 32 + 255) / 256, 256>>>(N);                            // 3 <- profiled
    gemm_mma<1><<<gemm_blocks, 256, SMEM>>>(                                    // 4
        (const float*)p_acc, (const unsigned char*)p_lwhi, (const unsigned char*)p_lwlo,
        lin_b, nullptr, out, N);
}

// round 10
// speedup vs baseline: 1.2589x; 1.0050x over previous
#include <cuda_runtime.h>
#include <cuda_bf16.h>
#include <cuda_fp16.h>
#include <cstdint>

#define N_NODES 100000
#define N_EDGES 1600000
#define CH 128          // IN_CH = HEADS*HID = OUT_CH = 128
#define HEADS 4
#define HID 32
#define NEG_SLOPE 0.2f
#define NBLK 148
#define CBS 1024

// ---------------- scratch (static device globals; no allocation) ----------------
__device__ __half g_h[(size_t)N_NODES * CH];      // x @ W, fp16 (25.6 MB)
__device__ float g_accum[(size_t)N_NODES * CH];   // normalized messages (51.2 MB)
__device__ float g_asrc[(size_t)N_NODES * HEADS]; // pre-scaled by log2(e)
__device__ float g_adst[(size_t)N_NODES * HEADS]; // pre-scaled by log2(e)
__device__ int   g_deg[N_NODES];
__device__ int   g_off[N_NODES];
__device__ int   g_cur[N_NODES];
__device__ int   g_srcs[N_EDGES];
__device__ int   g_bsum[NBLK];
__device__ unsigned g_c[8];                        // grid-barrier counters (zero-init)
// pre-swizzled bf16 hi/lo images of W^T and lin_w^T ([n][k] layout, 32KB each)
__device__ __align__(16) unsigned char g_whi[32768];
__device__ __align__(16) unsigned char g_wlo[32768];
__device__ __align__(16) unsigned char g_lwhi[32768];
__device__ __align__(16) unsigned char g_lwlo[32768];

#define LOG2E 1.4426950408889634f

// ---------------- helpers ----------------
__device__ __forceinline__ uint32_t s2u(const void* p) {
    uint32_t a;
    asm("{ .reg .u64 t; cvta.to.shared.u64 t, %1; cvt.u32.u64 %0, t; }" : "=r"(a) : "l"(p));
    return a;
}

// swizzled byte offset inside a [rows][128 bf16] tile (256B rows, XOR-16B-chunk swizzle)
__device__ __forceinline__ uint32_t swz(int row, int col) {
    return (uint32_t)(row * 256 + ((((col >> 3) ^ (row & 7))) << 4) + (col & 7) * 2);
}

#define LDSM4(r, addr) \
    asm volatile("ldmatrix.sync.aligned.m8n8.x4.shared.b16 {%0,%1,%2,%3}, [%4];" \
        : "=r"((r)[0]), "=r"((r)[1]), "=r"((r)[2]), "=r"((r)[3]) : "r"(addr))

#define MMA16816(d, a, b0, b1) \
    asm volatile("mma.sync.aligned.m16n8k16.row.col.f32.bf16.bf16.f32 " \
        "{%0,%1,%2,%3}, {%4,%5,%6,%7}, {%8,%9}, {%0,%1,%2,%3};" \
        : "+f"((d)[0]), "+f"((d)[1]), "+f"((d)[2]), "+f"((d)[3]) \
        : "r"((a)[0]), "r"((a)[1]), "r"((a)[2]), "r"((a)[3]), "r"(b0), "r"(b1))

// fast 2^x and leaky-relu
__device__ __forceinline__ float ex2f(float x) {
    float r;
    asm("ex2.approx.f32 %0, %1;" : "=f"(r) : "f"(x));
    return r;
}
__device__ __forceinline__ float lrelu(float e) {
    return fmaf(fminf(e, 0.f), -(1.f - NEG_SLOPE), e);
}

// ---------------- software grid barrier ----------------
__device__ __forceinline__ void gbar(int ph) {
    __syncthreads();
    if (threadIdx.x == 0) {
        __threadfence();
        atomicAdd(&g_c[ph], 1u);
        while (*(volatile unsigned*)&g_c[ph] < (unsigned)NBLK) { __nanosleep(64); }
        __threadfence();
    }
    __syncthreads();
}

// ---------------- fused CSR build ----------------
__global__ void __launch_bounds__(CBS, 1) csr_build(const int* __restrict__ ei, int E, int N)
{
    __shared__ int sm[CBS];
    const int b = blockIdx.x, t = threadIdx.x;
    const int gt = b * CBS + t;
    const int GS = NBLK * CBS;
    const int CHUNK = (N + NBLK - 1) / NBLK;
    const int base = b * CHUNK;

    for (int i = gt; i < N; i += GS) g_deg[i] = 0;
    gbar(0);

    for (int i = gt; i < E; i += GS) atomicAdd(&g_deg[ei[E + i]], 1);
    gbar(1);

    int myv = 0;
    if (t < CHUNK && base + t < N) myv = __ldcg(&g_deg[base + t]);
    sm[t] = myv;
    __syncthreads();
#pragma unroll
    for (int d = 1; d < CBS; d <<= 1) {
        int v2 = (t >= d) ? sm[t - d] : 0;
        __syncthreads();
        sm[t] += v2;
        __syncthreads();
    }
    int incl = sm[t];
    if (t < CHUNK && base + t < N) g_off[base + t] = incl - myv;
    if (t == CBS - 1) g_bsum[b] = incl;
    gbar(2);

    if (b == 0) {
        int v = (t < NBLK) ? __ldcg(&g_bsum[t]) : 0;
        sm[t] = v;
        __syncthreads();
#pragma unroll
        for (int d = 1; d < CBS; d <<= 1) {
            int v2 = (t >= d) ? sm[t - d] : 0;
            __syncthreads();
            sm[t] += v2;
            __syncthreads();
        }
        if (t < NBLK) g_bsum[t] = sm[t] - v;
    }
    gbar(3);

    {
        int boff = __ldcg(&g_bsum[b]);
        if (t < CHUNK && base + t < N) {
            int o = g_off[base + t] + boff;
            g_off[base + t] = o;
            g_cur[base + t] = o;
        }
    }
    gbar(4);

    for (int i = gt; i < E; i += GS) {
        int dst = ei[E + i];
        int pos = atomicAdd(&g_cur[dst], 1);
        g_srcs[pos] = ei[i];
    }
    gbar(5);

    if (b == 0 && t < 8) g_c[t] = 0;
}

// ---------------- prep: W^T and lin_w^T -> bf16 hi/lo, swizzled (one launch) ----------------
__global__ void prep_all(const float* __restrict__ W, const float* __restrict__ LW) {
    int idx = blockIdx.x * blockDim.x + threadIdx.x;   // 32768
    int m   = idx >> 14;
    int rem = idx & 16383;
    int n = rem >> 7, k = rem & 127;
    const float* src = m ? LW : W;
    unsigned char* dhi = m ? g_lwhi : g_whi;
    unsigned char* dlo = m ? g_lwlo : g_wlo;
    float v = src[k * CH + n];
    __nv_bfloat16 h = __float2bfloat16(v);
    __nv_bfloat16 l = __float2bfloat16(v - __bfloat162float(h));
    uint32_t o = swz(n, k);
    *reinterpret_cast<__nv_bfloat16*>(dhi + o) = h;
    *reinterpret_cast<__nv_bfloat16*>(dlo + o) = l;
}

// ---------------- tensor-core GEMM (split-bf16 3-product) ----------------
// MODE 0: gemm1 -> C = g_h (fp16) + fused a_src/a_dst epilogue (v0=att_s, v1=att_d)
// MODE 1: gemm2 -> C = out (fp32) with bias(v0) + ReLU
template<int MODE>
__global__ void __launch_bounds__(256, 2) gemm_mma(
    const float* __restrict__ A,
    const unsigned char* __restrict__ Bhi_g, const unsigned char* __restrict__ Blo_g,
    const float* __restrict__ v0, const float* __restrict__ v1,
    void* __restrict__ Cv, int M)
{
    extern __shared__ __align__(16) unsigned char smem[];
    // layout: A_hi 16K | A_lo 16K | B_hi 32K | B_lo 32K
    const uint32_t sb = s2u(smem);
    const int tid = threadIdx.x, lane = tid & 31, w = tid >> 5;
    const int row0 = blockIdx.x * 64;

    {
        const int4* bh = reinterpret_cast<const int4*>(Bhi_g);
        const int4* bl = reinterpret_cast<const int4*>(Blo_g);
        int4* dh = reinterpret_cast<int4*>(smem + 32768);
        int4* dl = reinterpret_cast<int4*>(smem + 65536);
#pragma unroll
        for (int u = 0; u < 8; ++u) {
            int f = tid + u * 256;
            dh[f] = bh[f];
            dl[f] = bl[f];
        }
    }

#pragma unroll
    for (int u = 0; u < 8; ++u) {
        int f = tid + u * 256;
        int r = f >> 5;
        int c = (f & 31) * 4;
        float4 v = make_float4(0.f, 0.f, 0.f, 0.f);
        if (row0 + r < M)
            v = *reinterpret_cast<const float4*>(&A[(size_t)(row0 + r) * CH + c]);
        __nv_bfloat162 h01 = __floats2bfloat162_rn(v.x, v.y);
        __nv_bfloat162 h23 = __floats2bfloat162_rn(v.z, v.w);
        __nv_bfloat162 lo01 = __floats2bfloat162_rn(v.x - __bfloat162float(h01.x),
                                                    v.y - __bfloat162float(h01.y));
        __nv_bfloat162 lo23 = __floats2bfloat162_rn(v.z - __bfloat162float(h23.x),
                                                    v.w - __bfloat162float(h23.y));
        uint32_t o = swz(r, c);
        uint2 uh, ul;
        uh.x = *reinterpret_cast<uint32_t*>(&h01);
        uh.y = *reinterpret_cast<uint32_t*>(&h23);
        ul.x = *reinterpret_cast<uint32_t*>(&lo01);
        ul.y = *reinterpret_cast<uint32_t*>(&lo23);
        *reinterpret_cast<uint2*>(smem + o)         = uh;
        *reinterpret_cast<uint2*>(smem + 16384 + o) = ul;
    }
    __syncthreads();

    const int wr = (w >> 1) * 16;
    const int wc = (w & 1) * 64;

    float acc[8][4];
#pragma unroll
    for (int j = 0; j < 8; ++j)
#pragma unroll
        for (int q = 0; q < 4; ++q) acc[j][q] = 0.f;

    const int arow  = wr + (lane & 7) + ((lane >> 3) & 1) * 8;
    const int asel  = lane >> 4;
    const int arow7 = arow & 7;
    const int bg_row = (lane & 7) + ((lane >> 4) & 1) * 8;
    const int bsel   = (lane >> 3) & 1;

#pragma unroll
    for (int kk = 0; kk < 8; ++kk) {
        uint32_t a_hi[4], a_lo[4];
        uint32_t aaddr = sb + (uint32_t)(arow * 256) +
                         (uint32_t)((((kk * 2 + asel) ^ arow7)) << 4);
        LDSM4(a_hi, aaddr);
        LDSM4(a_lo, aaddr + 16384);

        uint32_t b_hi[16], b_lo[16];
#pragma unroll
        for (int g = 0; g < 4; ++g) {
            int brow = wc + g * 16 + bg_row;
            uint32_t baddr = sb + 32768 + (uint32_t)(brow * 256) +
                             (uint32_t)((((kk * 2 + bsel) ^ (brow & 7))) << 4);
            LDSM4(&b_hi[g * 4], baddr);
            LDSM4(&b_lo[g * 4], baddr + 32768);
        }

        // 3 product passes; 8 independent accumulators inside each pass
        // (dependency distance 8, not 1 — keeps the tensor pipe fed)
#pragma unroll
        for (int j = 0; j < 8; ++j) {
            int i0 = (j >> 1) * 4 + (j & 1) * 2;
            MMA16816(acc[j], a_hi, b_hi[i0], b_hi[i0 + 1]);
        }
#pragma unroll
        for (int j = 0; j < 8; ++j) {
            int i0 = (j >> 1) * 4 + (j & 1) * 2;
            MMA16816(acc[j], a_hi, b_lo[i0], b_lo[i0 + 1]);
        }
#pragma unroll
        for (int j = 0; j < 8; ++j) {
            int i0 = (j >> 1) * 4 + (j & 1) * 2;
            MMA16816(acc[j], a_lo, b_hi[i0], b_hi[i0 + 1]);
        }
    }

    const int r_g = row0 + wr + (lane >> 2);
#pragma unroll
    for (int j = 0; j < 8; ++j) {
        int n0 = wc + j * 8 + (lane & 3) * 2;
        if (MODE == 1) {
            float* C = (float*)Cv;
            float b0 = __ldg(&v0[n0]), b1 = __ldg(&v0[n0 + 1]);
            float2 o0, o1;
            o0.x = fmaxf(acc[j][0] + b0, 0.f); o0.y = fmaxf(acc[j][1] + b1, 0.f);
            o1.x = fmaxf(acc[j][2] + b0, 0.f); o1.y = fmaxf(acc[j][3] + b1, 0.f);
            if (r_g < M)
                *reinterpret_cast<float2*>(&C[(size_t)r_g * CH + n0]) = o0;
            if (r_g + 8 < M)
                *reinterpret_cast<float2*>(&C[(size_t)(r_g + 8) * CH + n0]) = o1;
        } else {
            __half* C = (__half*)Cv;
            __half2 o0 = __float22half2_rn(make_float2(acc[j][0], acc[j][1]));
            __half2 o1 = __float22half2_rn(make_float2(acc[j][2], acc[j][3]));
            if (r_g < M)
                *reinterpret_cast<__half2*>(&C[(size_t)r_g * CH + n0]) = o0;
            if (r_g + 8 < M)
                *reinterpret_cast<__half2*>(&C[(size_t)(r_g + 8) * CH + n0]) = o1;
        }
    }

    if (MODE == 0) {
        // fused att projections: this warp covers heads (wc/32, wc/32+1)
        // stored PRE-SCALED by log2(e) so gather can use ex2 directly
        float ps[2][2] = {{0.f, 0.f}, {0.f, 0.f}};
        float pd[2][2] = {{0.f, 0.f}, {0.f, 0.f}};
#pragma unroll
        for (int j = 0; j < 8; ++j) {
            int n0 = wc + j * 8 + (lane & 3) * 2;
            float s0 = __ldg(&v0[n0]), s1 = __ldg(&v0[n0 + 1]);
            float d0 = __ldg(&v1[n0]), d1 = __ldg(&v1[n0 + 1]);
            int hh = j >> 2;
            ps[hh][0] += acc[j][0] * s0 + acc[j][1] * s1;
            ps[hh][1] += acc[j][2] * s0 + acc[j][3] * s1;
            pd[hh][0] += acc[j][0] * d0 + acc[j][1] * d1;
            pd[hh][1] += acc[j][2] * d0 + acc[j][3] * d1;
        }
#pragma unroll
        for (int o = 1; o < 4; o <<= 1) {
#pragma unroll
            for (int hh = 0; hh < 2; ++hh)
#pragma unroll
                for (int rh = 0; rh < 2; ++rh) {
                    ps[hh][rh] += __shfl_xor_sync(0xFFFFFFFFu, ps[hh][rh], o);
                    pd[hh][rh] += __shfl_xor_sync(0xFFFFFFFFu, pd[hh][rh], o);
                }
        }
        if ((lane & 3) == 0) {
            int h0 = wc >> 5;
            if (r_g < M) {
                g_asrc[(size_t)r_g * HEADS + h0]     = ps[0][0] * LOG2E;
                g_asrc[(size_t)r_g * HEADS + h0 + 1] = ps[1][0] * LOG2E;
                g_adst[(size_t)r_g * HEADS + h0]     = pd[0][0] * LOG2E;
                g_adst[(size_t)r_g * HEADS + h0 + 1] = pd[1][0] * LOG2E;
            }
            if (r_g + 8 < M) {
                g_asrc[(size_t)(r_g + 8) * HEADS + h0]     = ps[0][1] * LOG2E;
                g_asrc[(size_t)(r_g + 8) * HEADS + h0 + 1] = ps[1][1] * LOG2E;
                g_adst[(size_t)(r_g + 8) * HEADS + h0]     = pd[0][1] * LOG2E;
                g_adst[(size_t)(r_g + 8) * HEADS + h0 + 1] = pd[1][1] * LOG2E;
            }
        }
    }
}

// ---------------- gather: one warp per dst node, 4 edges in flight, fp16 h ----------------
// logits pre-scaled by log2(e); leakyrelu is positively homogeneous, so
// 2^lrelu(as'+ad') == exp(lrelu(as+ad)) exactly.
__device__ __forceinline__ void h4_to_f(uint2 u, float& f0, float& f1, float& f2, float& f3) {
    float2 a = __half22float2(*reinterpret_cast<__half2*>(&u.x));
    float2 b = __half22float2(*reinterpret_cast<__half2*>(&u.y));
    f0 = a.x; f1 = a.y; f2 = b.x; f3 = b.y;
}

__global__ void __launch_bounds__(256) gather_kernel(int N)
{
    int node = (blockIdx.x * blockDim.x + threadIdx.x) >> 5;
    if (node >= N) return;
    int lane = threadIdx.x & 31;
    int head = lane >> 3;

    int off = g_off[node];
    int deg = g_deg[node];

    float4 ad4 = *reinterpret_cast<const float4*>(&g_adst[(size_t)node * HEADS]);
    float ad_my = (lane & 16) ? ((lane & 8) ? ad4.w : ad4.z)
                              : ((lane & 8) ? ad4.y : ad4.x);

    float a0 = 0.f, a1 = 0.f, a2 = 0.f, a3 = 0.f;
    float s_my = 0.f;

    for (int base = 0; base < deg; base += 32) {
        int idx = 0;
        if (base + lane < deg) idx = g_srcs[off + base + lane];
        int cnt = min(32, deg - base);
        int j = 0;
        for (; j + 4 <= cnt; j += 4) {
            int s0 = __shfl_sync(0xFFFFFFFFu, idx, j);
            int s1 = __shfl_sync(0xFFFFFFFFu, idx, j + 1);
            int s2 = __shfl_sync(0xFFFFFFFFu, idx, j + 2);
            int s3 = __shfl_sync(0xFFFFFFFFu, idx, j + 3);
            float as0 = __ldg(&g_asrc[(size_t)s0 * HEADS + head]);
            float as1 = __ldg(&g_asrc[(size_t)s1 * HEADS + head]);
            float as2 = __ldg(&g_asrc[(size_t)s2 * HEADS + head]);
            float as3 = __ldg(&g_asrc[(size_t)s3 * HEADS + head]);
            uint2 u0 = *reinterpret_cast<const uint2*>(&g_h[(size_t)s0 * CH + lane * 4]);
            uint2 u1 = *reinterpret_cast<const uint2*>(&g_h[(size_t)s1 * CH + lane * 4]);
            uint2 u2 = *reinterpret_cast<const uint2*>(&g_h[(size_t)s2 * CH + lane * 4]);
            uint2 u3 = *reinterpret_cast<const uint2*>(&g_h[(size_t)s3 * CH + lane * 4]);

            float x0 = ex2f(lrelu(as0 + ad_my));
            float x1 = ex2f(lrelu(as1 + ad_my));
            float x2 = ex2f(lrelu(as2 + ad_my));
            float x3 = ex2f(lrelu(as3 + ad_my));

            float h0, h1, h2, h3;
            h4_to_f(u0, h0, h1, h2, h3);
            a0 = fmaf(x0, h0, a0); a1 = fmaf(x0, h1, a1);
            a2 = fmaf(x0, h2, a2); a3 = fmaf(x0, h3, a3);
            h4_to_f(u1, h0, h1, h2, h3);
            a0 = fmaf(x1, h0, a0); a1 = fmaf(x1, h1, a1);
            a2 = fmaf(x1, h2, a2); a3 = fmaf(x1, h3, a3);
            h4_to_f(u2, h0, h1, h2, h3);
            a0 = fmaf(x2, h0, a0); a1 = fmaf(x2, h1, a1);
            a2 = fmaf(x2, h2, a2); a3 = fmaf(x2, h3, a3);
            h4_to_f(u3, h0, h1, h2, h3);
            a0 = fmaf(x3, h0, a0); a1 = fmaf(x3, h1, a1);
            a2 = fmaf(x3, h2, a2); a3 = fmaf(x3, h3, a3);
            s_my += x0 + x1 + x2 + x3;
        }
        for (; j < cnt; ++j) {
            int src = __shfl_sync(0xFFFFFFFFu, idx, j);
            float as_my = __ldg(&g_asrc[(size_t)src * HEADS + head]);
            float ex = ex2f(lrelu(as_my + ad_my));
            uint2 u = *reinterpret_cast<const uint2*>(&g_h[(size_t)src * CH + lane * 4]);
            float h0, h1, h2, h3;
            h4_to_f(u, h0, h1, h2, h3);
            a0 = fmaf(ex, h0, a0);
            a1 = fmaf(ex, h1, a1);
            a2 = fmaf(ex, h2, a2);
            a3 = fmaf(ex, h3, a3);
            s_my += ex;
        }
    }

    float inv = 1.f / (s_my + 1e-16f);
    float4 o = make_float4(a0 * inv, a1 * inv, a2 * inv, a3 * inv);
    *reinterpret_cast<float4*>(&g_accum[(size_t)node * CH + lane * 4]) = o;
}

// ---------------- launch ----------------
extern "C" void kernel_launch(void* const* d_in, const int* in_sizes, int n_in,
                              void* d_out, int out_size)
{
    const float* x     = (const float*)d_in[0];
    const int*   ei    = (const int*)  d_in[1];
    const float* W     = (const float*)d_in[2];
    const float* att_s = (const float*)d_in[3];
    const float* att_d = (const float*)d_in[4];
    const float* lin_w = (const float*)d_in[5];
    const float* lin_b = (const float*)d_in[6];
    float* out = (float*)d_out;

    int N = in_sizes[0] / CH;    // 100000
    int E = in_sizes[1] / 2;     // 1600000

    void *p_h, *p_acc, *p_whi, *p_wlo, *p_lwhi, *p_lwlo;
    cudaGetSymbolAddress(&p_h, g_h);
    cudaGetSymbolAddress(&p_acc, g_accum);
    cudaGetSymbolAddress(&p_whi, g_whi);
    cudaGetSymbolAddress(&p_wlo, g_wlo);
    cudaGetSymbolAddress(&p_lwhi, g_lwhi);
    cudaGetSymbolAddress(&p_lwlo, g_lwlo);

    const int SMEM = 98304;
    cudaFuncSetAttribute(gemm_mma<0>, cudaFuncAttributeMaxDynamicSharedMemorySize, SMEM);
    cudaFuncSetAttribute(gemm_mma<1>, cudaFuncAttributeMaxDynamicSharedMemorySize, SMEM);

    int gemm_blocks = (N + 63) / 64;

    // fork: csr_build (side stream) || prep + gemm1 (main stream) — proven topology
    cudaStream_t s2;
    cudaStreamCreateWithFlags(&s2, cudaStreamNonBlocking);
    cudaEvent_t ev_fork, ev_join;
    cudaEventCreateWithFlags(&ev_fork, cudaEventDisableTiming);
    cudaEventCreateWithFlags(&ev_join, cudaEventDisableTiming);

    cudaEventRecord(ev_fork, 0);
    cudaStreamWaitEvent(s2, ev_fork, 0);
    csr_build<<<NBLK, CBS, 0, s2>>>(ei, E, N);                                  // 0
    cudaEventRecord(ev_join, s2);

    prep_all<<<128, 256>>>(W, lin_w);                                           // 1
    gemm_mma<0><<<gemm_blocks, 256, SMEM>>>(                                    // 2
        x, (const unsigned char*)p_whi, (const unsigned char*)p_wlo,
        att_s, att_d, p_h, N);

    cudaStreamWaitEvent(0, ev_join, 0);
    gather_kernel<<<(N * 32 + 255) / 256, 256>>>(N);                            // 3 <- profiled
    gemm_mma<1><<<gemm_blocks, 256, SMEM>>>(                                    // 4
        (const float*)p_acc, (const unsigned char*)p_lwhi, (const unsigned char*)p_lwlo,
        lin_b, nullptr, out, N);
}

// round 11
// speedup vs baseline: 1.3721x; 1.0899x over previous
#include <cuda_runtime.h>
#include <cuda_bf16.h>
#include <cuda_fp16.h>
#include <cstdint>

#define N_NODES 100000
#define N_EDGES 1600000
#define CH 128          // IN_CH = HEADS*HID = OUT_CH = 128
#define HEADS 4
#define HID 32
#define NEG_SLOPE 0.2f
#define NBLK 148
#define CBS 1024

// ---------------- scratch (static device globals; no allocation) ----------------
__device__ __half g_h[(size_t)N_NODES * CH];      // x @ W, fp16 (25.6 MB)
__device__ float g_accum[(size_t)N_NODES * CH];   // normalized messages (51.2 MB)
__device__ float g_asrc[(size_t)N_NODES * HEADS]; // pre-scaled by log2(e)
__device__ float g_adst[(size_t)N_NODES * HEADS]; // pre-scaled by log2(e)
__device__ int   g_deg[N_NODES];
__device__ int   g_off[N_NODES];
__device__ int   g_cur[N_NODES];
__device__ int   g_srcs[N_EDGES];
__device__ int   g_bsum[NBLK];
__device__ unsigned g_c[8];                        // grid-barrier counters (zero-init)
// pre-swizzled bf16 hi/lo images of W^T and lin_w^T ([n][k] layout, 32KB each)
__device__ __align__(16) unsigned char g_whi[32768];
__device__ __align__(16) unsigned char g_wlo[32768];
__device__ __align__(16) unsigned char g_lwhi[32768];
__device__ __align__(16) unsigned char g_lwlo[32768];

#define LOG2E 1.4426950408889634f

// ---------------- helpers ----------------
__device__ __forceinline__ uint32_t s2u(const void* p) {
    uint32_t a;
    asm("{ .reg .u64 t; cvta.to.shared.u64 t, %1; cvt.u32.u64 %0, t; }" : "=r"(a) : "l"(p));
    return a;
}

// swizzled byte offset inside a [rows][128 bf16] tile (256B rows, XOR-16B-chunk swizzle)
__device__ __forceinline__ uint32_t swz(int row, int col) {
    return (uint32_t)(row * 256 + ((((col >> 3) ^ (row & 7))) << 4) + (col & 7) * 2);
}

#define LDSM4(r, addr) \
    asm volatile("ldmatrix.sync.aligned.m8n8.x4.shared.b16 {%0,%1,%2,%3}, [%4];" \
        : "=r"((r)[0]), "=r"((r)[1]), "=r"((r)[2]), "=r"((r)[3]) : "r"(addr))

#define MMA16816(d, a, b0, b1) \
    asm volatile("mma.sync.aligned.m16n8k16.row.col.f32.bf16.bf16.f32 " \
        "{%0,%1,%2,%3}, {%4,%5,%6,%7}, {%8,%9}, {%0,%1,%2,%3};" \
        : "+f"((d)[0]), "+f"((d)[1]), "+f"((d)[2]), "+f"((d)[3]) \
        : "r"((a)[0]), "r"((a)[1]), "r"((a)[2]), "r"((a)[3]), "r"(b0), "r"(b1))

// fast 2^x and leaky-relu
__device__ __forceinline__ float ex2f(float x) {
    float r;
    asm("ex2.approx.f32 %0, %1;" : "=f"(r) : "f"(x));
    return r;
}
__device__ __forceinline__ float lrelu(float e) {
    return fmaf(fminf(e, 0.f), -(1.f - NEG_SLOPE), e);
}

// ---------------- software grid barrier ----------------
__device__ __forceinline__ void gbar(int ph) {
    __syncthreads();
    if (threadIdx.x == 0) {
        __threadfence();
        atomicAdd(&g_c[ph], 1u);
        while (*(volatile unsigned*)&g_c[ph] < (unsigned)NBLK) { __nanosleep(64); }
        __threadfence();
    }
    __syncthreads();
}

// ---------------- fused CSR build ----------------
__global__ void __launch_bounds__(CBS, 1) csr_build(const int* __restrict__ ei, int E, int N)
{
    __shared__ int sm[CBS];
    const int b = blockIdx.x, t = threadIdx.x;
    const int gt = b * CBS + t;
    const int GS = NBLK * CBS;
    const int CHUNK = (N + NBLK - 1) / NBLK;
    const int base = b * CHUNK;

    for (int i = gt; i < N; i += GS) g_deg[i] = 0;
    gbar(0);

    for (int i = gt; i < E; i += GS) atomicAdd(&g_deg[ei[E + i]], 1);
    gbar(1);

    int myv = 0;
    if (t < CHUNK && base + t < N) myv = __ldcg(&g_deg[base + t]);
    sm[t] = myv;
    __syncthreads();
#pragma unroll
    for (int d = 1; d < CBS; d <<= 1) {
        int v2 = (t >= d) ? sm[t - d] : 0;
        __syncthreads();
        sm[t] += v2;
        __syncthreads();
    }
    int incl = sm[t];
    if (t < CHUNK && base + t < N) g_off[base + t] = incl - myv;
    if (t == CBS - 1) g_bsum[b] = incl;
    gbar(2);

    if (b == 0) {
        int v = (t < NBLK) ? __ldcg(&g_bsum[t]) : 0;
        sm[t] = v;
        __syncthreads();
#pragma unroll
        for (int d = 1; d < CBS; d <<= 1) {
            int v2 = (t >= d) ? sm[t - d] : 0;
            __syncthreads();
            sm[t] += v2;
            __syncthreads();
        }
        if (t < NBLK) g_bsum[t] = sm[t] - v;
    }
    gbar(3);

    {
        int boff = __ldcg(&g_bsum[b]);
        if (t < CHUNK && base + t < N) {
            int o = g_off[base + t] + boff;
            g_off[base + t] = o;
            g_cur[base + t] = o;
        }
    }
    gbar(4);

    for (int i = gt; i < E; i += GS) {
        int dst = ei[E + i];
        int pos = atomicAdd(&g_cur[dst], 1);
        g_srcs[pos] = ei[i];
    }
    gbar(5);

    if (b == 0 && t < 8) g_c[t] = 0;
}

// ---------------- prep: W^T and lin_w^T -> bf16 hi/lo, swizzled (one launch) ----------------
__global__ void prep_all(const float* __restrict__ W, const float* __restrict__ LW) {
    int idx = blockIdx.x * blockDim.x + threadIdx.x;   // 32768
    int m   = idx >> 14;
    int rem = idx & 16383;
    int n = rem >> 7, k = rem & 127;
    const float* src = m ? LW : W;
    unsigned char* dhi = m ? g_lwhi : g_whi;
    unsigned char* dlo = m ? g_lwlo : g_wlo;
    float v = src[k * CH + n];
    __nv_bfloat16 h = __float2bfloat16(v);
    __nv_bfloat16 l = __float2bfloat16(v - __bfloat162float(h));
    uint32_t o = swz(n, k);
    *reinterpret_cast<__nv_bfloat16*>(dhi + o) = h;
    *reinterpret_cast<__nv_bfloat16*>(dlo + o) = l;
}

// ---------------- tensor-core GEMM (split-bf16 3-product), PERSISTENT blocks ----------------
// MODE 0: gemm1 -> C = g_h (fp16) + fused a_src/a_dst epilogue (v0=att_s, v1=att_d)
// MODE 1: gemm2 -> C = out (fp32) with bias(v0) + ReLU
// B tiles are copied into smem ONCE per block; block loops over row tiles.
template<int MODE>
__global__ void __launch_bounds__(256, 2) gemm_mma(
    const float* __restrict__ A,
    const unsigned char* __restrict__ Bhi_g, const unsigned char* __restrict__ Blo_g,
    const float* __restrict__ v0, const float* __restrict__ v1,
    void* __restrict__ Cv, int M)
{
    extern __shared__ __align__(16) unsigned char smem[];
    // layout: A_hi 16K | A_lo 16K | B_hi 32K | B_lo 32K
    const uint32_t sb = s2u(smem);
    const int tid = threadIdx.x, lane = tid & 31, w = tid >> 5;

    // copy B tiles once
    {
        const int4* bh = reinterpret_cast<const int4*>(Bhi_g);
        const int4* bl = reinterpret_cast<const int4*>(Blo_g);
        int4* dh = reinterpret_cast<int4*>(smem + 32768);
        int4* dl = reinterpret_cast<int4*>(smem + 65536);
#pragma unroll
        for (int u = 0; u < 8; ++u) {
            int f = tid + u * 256;
            dh[f] = bh[f];
            dl[f] = bl[f];
        }
    }

    const int wr = (w >> 1) * 16;
    const int wc = (w & 1) * 64;
    const int arow  = wr + (lane & 7) + ((lane >> 3) & 1) * 8;
    const int asel  = lane >> 4;
    const int arow7 = arow & 7;
    const int bg_row = (lane & 7) + ((lane >> 4) & 1) * 8;
    const int bsel   = (lane >> 3) & 1;

    const int ntiles = (M + 63) / 64;
    for (int tile = blockIdx.x; tile < ntiles; tile += gridDim.x) {
        const int row0 = tile * 64;

        __syncthreads();   // protect A smem from previous iteration's readers

        // stage A tile: fp32 -> bf16 hi/lo, swizzled
#pragma unroll
        for (int u = 0; u < 8; ++u) {
            int f = tid + u * 256;
            int r = f >> 5;
            int c = (f & 31) * 4;
            float4 v = make_float4(0.f, 0.f, 0.f, 0.f);
            if (row0 + r < M)
                v = *reinterpret_cast<const float4*>(&A[(size_t)(row0 + r) * CH + c]);
            __nv_bfloat162 h01 = __floats2bfloat162_rn(v.x, v.y);
            __nv_bfloat162 h23 = __floats2bfloat162_rn(v.z, v.w);
            __nv_bfloat162 lo01 = __floats2bfloat162_rn(v.x - __bfloat162float(h01.x),
                                                        v.y - __bfloat162float(h01.y));
            __nv_bfloat162 lo23 = __floats2bfloat162_rn(v.z - __bfloat162float(h23.x),
                                                        v.w - __bfloat162float(h23.y));
            uint32_t o = swz(r, c);
            uint2 uh, ul;
            uh.x = *reinterpret_cast<uint32_t*>(&h01);
            uh.y = *reinterpret_cast<uint32_t*>(&h23);
            ul.x = *reinterpret_cast<uint32_t*>(&lo01);
            ul.y = *reinterpret_cast<uint32_t*>(&lo23);
            *reinterpret_cast<uint2*>(smem + o)         = uh;
            *reinterpret_cast<uint2*>(smem + 16384 + o) = ul;
        }
        __syncthreads();

        float acc[8][4];
#pragma unroll
        for (int j = 0; j < 8; ++j)
#pragma unroll
            for (int q = 0; q < 4; ++q) acc[j][q] = 0.f;

#pragma unroll
        for (int kk = 0; kk < 8; ++kk) {
            uint32_t a_hi[4], a_lo[4];
            uint32_t aaddr = sb + (uint32_t)(arow * 256) +
                             (uint32_t)((((kk * 2 + asel) ^ arow7)) << 4);
            LDSM4(a_hi, aaddr);
            LDSM4(a_lo, aaddr + 16384);

            uint32_t b_hi[16], b_lo[16];
#pragma unroll
            for (int g = 0; g < 4; ++g) {
                int brow = wc + g * 16 + bg_row;
                uint32_t baddr = sb + 32768 + (uint32_t)(brow * 256) +
                                 (uint32_t)((((kk * 2 + bsel) ^ (brow & 7))) << 4);
                LDSM4(&b_hi[g * 4], baddr);
                LDSM4(&b_lo[g * 4], baddr + 32768);
            }

#pragma unroll
            for (int j = 0; j < 8; ++j) {
                int i0 = (j >> 1) * 4 + (j & 1) * 2;
                MMA16816(acc[j], a_hi, b_hi[i0], b_hi[i0 + 1]);
            }
#pragma unroll
            for (int j = 0; j < 8; ++j) {
                int i0 = (j >> 1) * 4 + (j & 1) * 2;
                MMA16816(acc[j], a_hi, b_lo[i0], b_lo[i0 + 1]);
            }
#pragma unroll
            for (int j = 0; j < 8; ++j) {
                int i0 = (j >> 1) * 4 + (j & 1) * 2;
                MMA16816(acc[j], a_lo, b_hi[i0], b_hi[i0 + 1]);
            }
        }

        const int r_g = row0 + wr + (lane >> 2);
#pragma unroll
        for (int j = 0; j < 8; ++j) {
            int n0 = wc + j * 8 + (lane & 3) * 2;
            if (MODE == 1) {
                float* C = (float*)Cv;
                float b0 = __ldg(&v0[n0]), b1 = __ldg(&v0[n0 + 1]);
                float2 o0, o1;
                o0.x = fmaxf(acc[j][0] + b0, 0.f); o0.y = fmaxf(acc[j][1] + b1, 0.f);
                o1.x = fmaxf(acc[j][2] + b0, 0.f); o1.y = fmaxf(acc[j][3] + b1, 0.f);
                if (r_g < M)
                    *reinterpret_cast<float2*>(&C[(size_t)r_g * CH + n0]) = o0;
                if (r_g + 8 < M)
                    *reinterpret_cast<float2*>(&C[(size_t)(r_g + 8) * CH + n0]) = o1;
            } else {
                __half* C = (__half*)Cv;
                __half2 o0 = __float22half2_rn(make_float2(acc[j][0], acc[j][1]));
                __half2 o1 = __float22half2_rn(make_float2(acc[j][2], acc[j][3]));
                if (r_g < M)
                    *reinterpret_cast<__half2*>(&C[(size_t)r_g * CH + n0]) = o0;
                if (r_g + 8 < M)
                    *reinterpret_cast<__half2*>(&C[(size_t)(r_g + 8) * CH + n0]) = o1;
            }
        }

        if (MODE == 0) {
            // fused att projections, pre-scaled by log2(e)
            float ps[2][2] = {{0.f, 0.f}, {0.f, 0.f}};
            float pd[2][2] = {{0.f, 0.f}, {0.f, 0.f}};
#pragma unroll
            for (int j = 0; j < 8; ++j) {
                int n0 = wc + j * 8 + (lane & 3) * 2;
                float s0 = __ldg(&v0[n0]), s1 = __ldg(&v0[n0 + 1]);
                float d0 = __ldg(&v1[n0]), d1 = __ldg(&v1[n0 + 1]);
                int hh = j >> 2;
                ps[hh][0] += acc[j][0] * s0 + acc[j][1] * s1;
                ps[hh][1] += acc[j][2] * s0 + acc[j][3] * s1;
                pd[hh][0] += acc[j][0] * d0 + acc[j][1] * d1;
                pd[hh][1] += acc[j][2] * d0 + acc[j][3] * d1;
            }
#pragma unroll
            for (int o = 1; o < 4; o <<= 1) {
#pragma unroll
                for (int hh = 0; hh < 2; ++hh)
#pragma unroll
                    for (int rh = 0; rh < 2; ++rh) {
                        ps[hh][rh] += __shfl_xor_sync(0xFFFFFFFFu, ps[hh][rh], o);
                        pd[hh][rh] += __shfl_xor_sync(0xFFFFFFFFu, pd[hh][rh], o);
                    }
            }
            if ((lane & 3) == 0) {
                int h0 = wc >> 5;
                if (r_g < M) {
                    g_asrc[(size_t)r_g * HEADS + h0]     = ps[0][0] * LOG2E;
                    g_asrc[(size_t)r_g * HEADS + h0 + 1] = ps[1][0] * LOG2E;
                    g_adst[(size_t)r_g * HEADS + h0]     = pd[0][0] * LOG2E;
                    g_adst[(size_t)r_g * HEADS + h0 + 1] = pd[1][0] * LOG2E;
                }
                if (r_g + 8 < M) {
                    g_asrc[(size_t)(r_g + 8) * HEADS + h0]     = ps[0][1] * LOG2E;
                    g_asrc[(size_t)(r_g + 8) * HEADS + h0 + 1] = ps[1][1] * LOG2E;
                    g_adst[(size_t)(r_g + 8) * HEADS + h0]     = pd[0][1] * LOG2E;
                    g_adst[(size_t)(r_g + 8) * HEADS + h0 + 1] = pd[1][1] * LOG2E;
                }
            }
        }
    }
}

// ---------------- gather v2: one warp per dst node, 2 edges/step, 8 ch/lane ----------------
// lanes 0-15 process even step-edges, lanes 16-31 odd; lane owns channels [sub*8, sub*8+8).
// logits pre-scaled by log2(e); 2^lrelu == exp(lrelu) by positive homogeneity.
__global__ void __launch_bounds__(256) gather_kernel(int N)
{
    int node = (blockIdx.x * blockDim.x + threadIdx.x) >> 5;
    if (node >= N) return;
    const int lane = threadIdx.x & 31;
    const int sub  = lane & 15;        // channel group
    const int half = lane >> 4;        // edge parity within a step pair
    const int head = sub >> 2;
    const int chan = sub * 8;

    const int off = g_off[node];
    const int deg = g_deg[node];

    const float ad_my = __ldg(&g_adst[(size_t)node * HEADS + head]);

    float acc[8];
#pragma unroll
    for (int c = 0; c < 8; ++c) acc[c] = 0.f;
    float s_my = 0.f;

    for (int base = 0; base < deg; base += 32) {
        int idx = 0;
        if (base + lane < deg) idx = g_srcs[off + base + lane];
        int cnt = min(32, deg - base);
        for (int j = 0; j < cnt; j += 4) {
            int e0 = j + half;
            int e1 = j + 2 + half;
            int s0 = __shfl_sync(0xFFFFFFFFu, idx, e0);
            int s1 = __shfl_sync(0xFFFFFFFFu, idx, e1);
            // issue all loads before consumers
            float as0 = __ldg(&g_asrc[(size_t)s0 * HEADS + head]);
            float as1 = __ldg(&g_asrc[(size_t)s1 * HEADS + head]);
            uint4 u0 = *reinterpret_cast<const uint4*>(&g_h[(size_t)s0 * CH + chan]);
            uint4 u1 = *reinterpret_cast<const uint4*>(&g_h[(size_t)s1 * CH + chan]);

            float x0 = (e0 < cnt) ? ex2f(lrelu(as0 + ad_my)) : 0.f;
            float x1 = (e1 < cnt) ? ex2f(lrelu(as1 + ad_my)) : 0.f;

            float2 f;
            f = __half22float2(*reinterpret_cast<__half2*>(&u0.x));
            acc[0] = fmaf(x0, f.x, acc[0]); acc[1] = fmaf(x0, f.y, acc[1]);
            f = __half22float2(*reinterpret_cast<__half2*>(&u0.y));
            acc[2] = fmaf(x0, f.x, acc[2]); acc[3] = fmaf(x0, f.y, acc[3]);
            f = __half22float2(*reinterpret_cast<__half2*>(&u0.z));
            acc[4] = fmaf(x0, f.x, acc[4]); acc[5] = fmaf(x0, f.y, acc[5]);
            f = __half22float2(*reinterpret_cast<__half2*>(&u0.w));
            acc[6] = fmaf(x0, f.x, acc[6]); acc[7] = fmaf(x0, f.y, acc[7]);

            f = __half22float2(*reinterpret_cast<__half2*>(&u1.x));
            acc[0] = fmaf(x1, f.x, acc[0]); acc[1] = fmaf(x1, f.y, acc[1]);
            f = __half22float2(*reinterpret_cast<__half2*>(&u1.y));
            acc[2] = fmaf(x1, f.x, acc[2]); acc[3] = fmaf(x1, f.y, acc[3]);
            f = __half22float2(*reinterpret_cast<__half2*>(&u1.z));
            acc[4] = fmaf(x1, f.x, acc[4]); acc[5] = fmaf(x1, f.y, acc[5]);
            f = __half22float2(*reinterpret_cast<__half2*>(&u1.w));
            acc[6] = fmaf(x1, f.x, acc[6]); acc[7] = fmaf(x1, f.y, acc[7]);

            s_my += x0 + x1;
        }
    }

    // cross-half reduction (half 0 edges + half 1 edges)
#pragma unroll
    for (int c = 0; c < 8; ++c)
        acc[c] += __shfl_xor_sync(0xFFFFFFFFu, acc[c], 16);
    s_my += __shfl_xor_sync(0xFFFFFFFFu, s_my, 16);

    if (half == 0) {
        float inv = 1.f / (s_my + 1e-16f);
        float4 o0 = make_float4(acc[0] * inv, acc[1] * inv, acc[2] * inv, acc[3] * inv);
        float4 o1 = make_float4(acc[4] * inv, acc[5] * inv, acc[6] * inv, acc[7] * inv);
        float* dst = &g_accum[(size_t)node * CH + chan];
        *reinterpret_cast<float4*>(dst)     = o0;
        *reinterpret_cast<float4*>(dst + 4) = o1;
    }
}

// ---------------- launch ----------------
extern "C" void kernel_launch(void* const* d_in, const int* in_sizes, int n_in,
                              void* d_out, int out_size)
{
    const float* x     = (const float*)d_in[0];
    const int*   ei    = (const int*)  d_in[1];
    const float* W     = (const float*)d_in[2];
    const float* att_s = (const float*)d_in[3];
    const float* att_d = (const float*)d_in[4];
    const float* lin_w = (const float*)d_in[5];
    const float* lin_b = (const float*)d_in[6];
    float* out = (float*)d_out;

    int N = in_sizes[0] / CH;    // 100000
    int E = in_sizes[1] / 2;     // 1600000

    void *p_h, *p_acc, *p_whi, *p_wlo, *p_lwhi, *p_lwlo;
    cudaGetSymbolAddress(&p_h, g_h);
    cudaGetSymbolAddress(&p_acc, g_accum);
    cudaGetSymbolAddress(&p_whi, g_whi);
    cudaGetSymbolAddress(&p_wlo, g_wlo);
    cudaGetSymbolAddress(&p_lwhi, g_lwhi);
    cudaGetSymbolAddress(&p_lwlo, g_lwlo);

    const int SMEM = 98304;
    cudaFuncSetAttribute(gemm_mma<0>, cudaFuncAttributeMaxDynamicSharedMemorySize, SMEM);
    cudaFuncSetAttribute(gemm_mma<1>, cudaFuncAttributeMaxDynamicSharedMemorySize, SMEM);

    int ntiles = (N + 63) / 64;
    int gemm_blocks = (ntiles < 296) ? ntiles : 296;   // persistent, 2/SM

    // fork: csr_build (side stream) || prep + gemm1 (main stream) — proven topology
    cudaStream_t s2;
    cudaStreamCreateWithFlags(&s2, cudaStreamNonBlocking);
    cudaEvent_t ev_fork, ev_join;
    cudaEventCreateWithFlags(&ev_fork, cudaEventDisableTiming);
    cudaEventCreateWithFlags(&ev_join, cudaEventDisableTiming);

    cudaEventRecord(ev_fork, 0);
    cudaStreamWaitEvent(s2, ev_fork, 0);
    csr_build<<<NBLK, CBS, 0, s2>>>(ei, E, N);                                  // 0
    cudaEventRecord(ev_join, s2);

    prep_all<<<128, 256>>>(W, lin_w);                                           // 1
    gemm_mma<0><<<gemm_blocks, 256, SMEM>>>(                                    // 2
        x, (const unsigned char*)p_whi, (const unsigned char*)p_wlo,
        att_s, att_d, p_h, N);

    cudaStreamWaitEvent(0, ev_join, 0);
    gather_kernel<<<(N * 32 + 255) / 256, 256>>>(N);                            // 3 <- profiled
    gemm_mma<1><<<gemm_blocks, 256, SMEM>>>(                                    // 4
        (const float*)p_acc, (const unsigned char*)p_lwhi, (const unsigned char*)p_lwlo,
        lin_b, nullptr, out, N);
}

// round 12
// speedup vs baseline: 1.4128x; 1.0297x over previous
#include <cuda_runtime.h>
#include <cuda_bf16.h>
#include <cuda_fp16.h>
#include <cstdint>

#define N_NODES 100000
#define N_EDGES 1600000
#define CH 128          // IN_CH = HEADS*HID = OUT_CH = 128
#define HEADS 4
#define HID 32
#define NEG_SLOPE 0.2f
#define NBLK 148
#define CBS 1024

// ---------------- scratch (static device globals; no allocation) ----------------
__device__ __half g_h[(size_t)N_NODES * CH];      // x @ W, fp16 (25.6 MB)
__device__ float g_accum[(size_t)N_NODES * CH];   // normalized messages (51.2 MB)
__device__ float g_asrc[(size_t)N_NODES * HEADS]; // pre-scaled by log2(e)
__device__ float g_adst[(size_t)N_NODES * HEADS]; // pre-scaled by log2(e)
__device__ int   g_deg[N_NODES];
__device__ int   g_off[N_NODES];
__device__ int   g_pos[N_EDGES];                  // per-edge slot within its dst list
__device__ int   g_srcs[N_EDGES];
__device__ int   g_bsum[NBLK];
__device__ unsigned g_c[8];                        // grid-barrier counters (zero-init)
// pre-swizzled bf16 hi/lo images of W^T and lin_w^T ([n][k] layout, 32KB each)
__device__ __align__(16) unsigned char g_whi[32768];
__device__ __align__(16) unsigned char g_wlo[32768];
__device__ __align__(16) unsigned char g_lwhi[32768];
__device__ __align__(16) unsigned char g_lwlo[32768];

#define LOG2E 1.4426950408889634f

// ---------------- helpers ----------------
__device__ __forceinline__ uint32_t s2u(const void* p) {
    uint32_t a;
    asm("{ .reg .u64 t; cvta.to.shared.u64 t, %1; cvt.u32.u64 %0, t; }" : "=r"(a) : "l"(p));
    return a;
}

// swizzled byte offset inside a [rows][128 bf16] tile (256B rows, XOR-16B-chunk swizzle)
__device__ __forceinline__ uint32_t swz(int row, int col) {
    return (uint32_t)(row * 256 + ((((col >> 3) ^ (row & 7))) << 4) + (col & 7) * 2);
}

#define LDSM4(r, addr) \
    asm volatile("ldmatrix.sync.aligned.m8n8.x4.shared.b16 {%0,%1,%2,%3}, [%4];" \
        : "=r"((r)[0]), "=r"((r)[1]), "=r"((r)[2]), "=r"((r)[3]) : "r"(addr))

#define MMA16816(d, a, b0, b1) \
    asm volatile("mma.sync.aligned.m16n8k16.row.col.f32.bf16.bf16.f32 " \
        "{%0,%1,%2,%3}, {%4,%5,%6,%7}, {%8,%9}, {%0,%1,%2,%3};" \
        : "+f"((d)[0]), "+f"((d)[1]), "+f"((d)[2]), "+f"((d)[3]) \
        : "r"((a)[0]), "r"((a)[1]), "r"((a)[2]), "r"((a)[3]), "r"(b0), "r"(b1))

// fast 2^x and leaky-relu
__device__ __forceinline__ float ex2f(float x) {
    float r;
    asm("ex2.approx.f32 %0, %1;" : "=f"(r) : "f"(x));
    return r;
}
__device__ __forceinline__ float lrelu(float e) {
    return fmaf(fminf(e, 0.f), -(1.f - NEG_SLOPE), e);
}

// ---------------- software grid barrier ----------------
__device__ __forceinline__ void gbar(int ph) {
    __syncthreads();
    if (threadIdx.x == 0) {
        __threadfence();
        atomicAdd(&g_c[ph], 1u);
        while (*(volatile unsigned*)&g_c[ph] < (unsigned)NBLK) { __nanosleep(64); }
        __threadfence();
    }
    __syncthreads();
}

// ---------------- fused CSR build (pos-recording; atomic-free placement) ----------------
__global__ void __launch_bounds__(CBS, 1) csr_build(const int* __restrict__ ei, int E, int N)
{
    __shared__ int sm[CBS];
    const int b = blockIdx.x, t = threadIdx.x;
    const int gt = b * CBS + t;
    const int GS = NBLK * CBS;
    const int CHUNK = (N + NBLK - 1) / NBLK;
    const int base = b * CHUNK;

    for (int i = gt; i < N; i += GS) g_deg[i] = 0;
    gbar(0);

    // histogram by dst, recording each edge's slot within its dst list
    for (int i = gt; i < E; i += GS) {
        int pos = atomicAdd(&g_deg[ei[E + i]], 1);
        g_pos[i] = pos;
    }
    gbar(1);

    int myv = 0;
    if (t < CHUNK && base + t < N) myv = __ldcg(&g_deg[base + t]);
    sm[t] = myv;
    __syncthreads();
#pragma unroll
    for (int d = 1; d < CBS; d <<= 1) {
        int v2 = (t >= d) ? sm[t - d] : 0;
        __syncthreads();
        sm[t] += v2;
        __syncthreads();
    }
    int incl = sm[t];
    if (t < CHUNK && base + t < N) g_off[base + t] = incl - myv;
    if (t == CBS - 1) g_bsum[b] = incl;
    gbar(2);

    if (b == 0) {
        int v = (t < NBLK) ? __ldcg(&g_bsum[t]) : 0;
        sm[t] = v;
        __syncthreads();
#pragma unroll
        for (int d = 1; d < CBS; d <<= 1) {
            int v2 = (t >= d) ? sm[t - d] : 0;
            __syncthreads();
            sm[t] += v2;
            __syncthreads();
        }
        if (t < NBLK) g_bsum[t] = sm[t] - v;
    }
    gbar(3);

    {
        int boff = __ldcg(&g_bsum[b]);
        if (t < CHUNK && base + t < N)
            g_off[base + t] += boff;
    }
    gbar(4);

    // atomic-free placement
    for (int i = gt; i < E; i += GS) {
        int dst = ei[E + i];
        g_srcs[__ldcg(&g_off[dst]) + g_pos[i]] = ei[i];
    }
    gbar(5);

    if (b == 0 && t < 8) g_c[t] = 0;
}

// ---------------- prep: W^T and lin_w^T -> bf16 hi/lo, swizzled (one launch) ----------------
__global__ void prep_all(const float* __restrict__ W, const float* __restrict__ LW) {
    int idx = blockIdx.x * blockDim.x + threadIdx.x;   // 32768
    int m   = idx >> 14;
    int rem = idx & 16383;
    int n = rem >> 7, k = rem & 127;
    const float* src = m ? LW : W;
    unsigned char* dhi = m ? g_lwhi : g_whi;
    unsigned char* dlo = m ? g_lwlo : g_wlo;
    float v = src[k * CH + n];
    __nv_bfloat16 h = __float2bfloat16(v);
    __nv_bfloat16 l = __float2bfloat16(v - __bfloat162float(h));
    uint32_t o = swz(n, k);
    *reinterpret_cast<__nv_bfloat16*>(dhi + o) = h;
    *reinterpret_cast<__nv_bfloat16*>(dlo + o) = l;
}

// ---------------- tensor-core GEMM (split-bf16 3-product), PERSISTENT blocks ----------------
// MODE 0: gemm1 -> C = g_h (fp16) + fused a_src/a_dst epilogue (v0=att_s, v1=att_d)
// MODE 1: gemm2 -> C = out (fp32) with bias(v0) + ReLU
template<int MODE>
__global__ void __launch_bounds__(256, 2) gemm_mma(
    const float* __restrict__ A,
    const unsigned char* __restrict__ Bhi_g, const unsigned char* __restrict__ Blo_g,
    const float* __restrict__ v0, const float* __restrict__ v1,
    void* __restrict__ Cv, int M)
{
    extern __shared__ __align__(16) unsigned char smem[];
    // layout: A_hi 16K | A_lo 16K | B_hi 32K | B_lo 32K
    const uint32_t sb = s2u(smem);
    const int tid = threadIdx.x, lane = tid & 31, w = tid >> 5;

    // copy B tiles once
    {
        const int4* bh = reinterpret_cast<const int4*>(Bhi_g);
        const int4* bl = reinterpret_cast<const int4*>(Blo_g);
        int4* dh = reinterpret_cast<int4*>(smem + 32768);
        int4* dl = reinterpret_cast<int4*>(smem + 65536);
#pragma unroll
        for (int u = 0; u < 8; ++u) {
            int f = tid + u * 256;
            dh[f] = bh[f];
            dl[f] = bl[f];
        }
    }

    const int wr = (w >> 1) * 16;
    const int wc = (w & 1) * 64;
    const int arow  = wr + (lane & 7) + ((lane >> 3) & 1) * 8;
    const int asel  = lane >> 4;
    const int arow7 = arow & 7;
    const int bg_row = (lane & 7) + ((lane >> 4) & 1) * 8;
    const int bsel   = (lane >> 3) & 1;

    const int ntiles = (M + 63) / 64;
    for (int tile = blockIdx.x; tile < ntiles; tile += gridDim.x) {
        const int row0 = tile * 64;

        __syncthreads();   // protect A smem from previous iteration's readers

        // stage A tile: fp32 -> bf16 hi/lo, swizzled
#pragma unroll
        for (int u = 0; u < 8; ++u) {
            int f = tid + u * 256;
            int r = f >> 5;
            int c = (f & 31) * 4;
            float4 v = make_float4(0.f, 0.f, 0.f, 0.f);
            if (row0 + r < M)
                v = *reinterpret_cast<const float4*>(&A[(size_t)(row0 + r) * CH + c]);
            __nv_bfloat162 h01 = __floats2bfloat162_rn(v.x, v.y);
            __nv_bfloat162 h23 = __floats2bfloat162_rn(v.z, v.w);
            __nv_bfloat162 lo01 = __floats2bfloat162_rn(v.x - __bfloat162float(h01.x),
                                                        v.y - __bfloat162float(h01.y));
            __nv_bfloat162 lo23 = __floats2bfloat162_rn(v.z - __bfloat162float(h23.x),
                                                        v.w - __bfloat162float(h23.y));
            uint32_t o = swz(r, c);
            uint2 uh, ul;
            uh.x = *reinterpret_cast<uint32_t*>(&h01);
            uh.y = *reinterpret_cast<uint32_t*>(&h23);
            ul.x = *reinterpret_cast<uint32_t*>(&lo01);
            ul.y = *reinterpret_cast<uint32_t*>(&lo23);
            *reinterpret_cast<uint2*>(smem + o)         = uh;
            *reinterpret_cast<uint2*>(smem + 16384 + o) = ul;
        }
        __syncthreads();

        float acc[8][4];
#pragma unroll
        for (int j = 0; j < 8; ++j)
#pragma unroll
            for (int q = 0; q < 4; ++q) acc[j][q] = 0.f;

#pragma unroll
        for (int kk = 0; kk < 8; ++kk) {
            uint32_t a_hi[4], a_lo[4];
            uint32_t aaddr = sb + (uint32_t)(arow * 256) +
                             (uint32_t)((((kk * 2 + asel) ^ arow7)) << 4);
            LDSM4(a_hi, aaddr);
            LDSM4(a_lo, aaddr + 16384);

            uint32_t b_hi[16], b_lo[16];
#pragma unroll
            for (int g = 0; g < 4; ++g) {
                int brow = wc + g * 16 + bg_row;
                uint32_t baddr = sb + 32768 + (uint32_t)(brow * 256) +
                                 (uint32_t)((((kk * 2 + bsel) ^ (brow & 7))) << 4);
                LDSM4(&b_hi[g * 4], baddr);
                LDSM4(&b_lo[g * 4], baddr + 32768);
            }

#pragma unroll
            for (int j = 0; j < 8; ++j) {
                int i0 = (j >> 1) * 4 + (j & 1) * 2;
                MMA16816(acc[j], a_hi, b_hi[i0], b_hi[i0 + 1]);
            }
#pragma unroll
            for (int j = 0; j < 8; ++j) {
                int i0 = (j >> 1) * 4 + (j & 1) * 2;
                MMA16816(acc[j], a_hi, b_lo[i0], b_lo[i0 + 1]);
            }
#pragma unroll
            for (int j = 0; j < 8; ++j) {
                int i0 = (j >> 1) * 4 + (j & 1) * 2;
                MMA16816(acc[j], a_lo, b_hi[i0], b_hi[i0 + 1]);
            }
        }

        const int r_g = row0 + wr + (lane >> 2);
#pragma unroll
        for (int j = 0; j < 8; ++j) {
            int n0 = wc + j * 8 + (lane & 3) * 2;
            if (MODE == 1) {
                float* C = (float*)Cv;
                float b0 = __ldg(&v0[n0]), b1 = __ldg(&v0[n0 + 1]);
                float2 o0, o1;
                o0.x = fmaxf(acc[j][0] + b0, 0.f); o0.y = fmaxf(acc[j][1] + b1, 0.f);
                o1.x = fmaxf(acc[j][2] + b0, 0.f); o1.y = fmaxf(acc[j][3] + b1, 0.f);
                if (r_g < M)
                    *reinterpret_cast<float2*>(&C[(size_t)r_g * CH + n0]) = o0;
                if (r_g + 8 < M)
                    *reinterpret_cast<float2*>(&C[(size_t)(r_g + 8) * CH + n0]) = o1;
            } else {
                __half* C = (__half*)Cv;
                __half2 o0 = __float22half2_rn(make_float2(acc[j][0], acc[j][1]));
                __half2 o1 = __float22half2_rn(make_float2(acc[j][2], acc[j][3]));
                if (r_g < M)
                    *reinterpret_cast<__half2*>(&C[(size_t)r_g * CH + n0]) = o0;
                if (r_g + 8 < M)
                    *reinterpret_cast<__half2*>(&C[(size_t)(r_g + 8) * CH + n0]) = o1;
            }
        }

        if (MODE == 0) {
            // fused att projections, pre-scaled by log2(e)
            float ps[2][2] = {{0.f, 0.f}, {0.f, 0.f}};
            float pd[2][2] = {{0.f, 0.f}, {0.f, 0.f}};
#pragma unroll
            for (int j = 0; j < 8; ++j) {
                int n0 = wc + j * 8 + (lane & 3) * 2;
                float s0 = __ldg(&v0[n0]), s1 = __ldg(&v0[n0 + 1]);
                float d0 = __ldg(&v1[n0]), d1 = __ldg(&v1[n0 + 1]);
                int hh = j >> 2;
                ps[hh][0] += acc[j][0] * s0 + acc[j][1] * s1;
                ps[hh][1] += acc[j][2] * s0 + acc[j][3] * s1;
                pd[hh][0] += acc[j][0] * d0 + acc[j][1] * d1;
                pd[hh][1] += acc[j][2] * d0 + acc[j][3] * d1;
            }
#pragma unroll
            for (int o = 1; o < 4; o <<= 1) {
#pragma unroll
                for (int hh = 0; hh < 2; ++hh)
#pragma unroll
                    for (int rh = 0; rh < 2; ++rh) {
                        ps[hh][rh] += __shfl_xor_sync(0xFFFFFFFFu, ps[hh][rh], o);
                        pd[hh][rh] += __shfl_xor_sync(0xFFFFFFFFu, pd[hh][rh], o);
                    }
            }
            if ((lane & 3) == 0) {
                int h0 = wc >> 5;
                if (r_g < M) {
                    g_asrc[(size_t)r_g * HEADS + h0]     = ps[0][0] * LOG2E;
                    g_asrc[(size_t)r_g * HEADS + h0 + 1] = ps[1][0] * LOG2E;
                    g_adst[(size_t)r_g * HEADS + h0]     = pd[0][0] * LOG2E;
                    g_adst[(size_t)r_g * HEADS + h0 + 1] = pd[1][0] * LOG2E;
                }
                if (r_g + 8 < M) {
                    g_asrc[(size_t)(r_g + 8) * HEADS + h0]     = ps[0][1] * LOG2E;
                    g_asrc[(size_t)(r_g + 8) * HEADS + h0 + 1] = ps[1][1] * LOG2E;
                    g_adst[(size_t)(r_g + 8) * HEADS + h0]     = pd[0][1] * LOG2E;
                    g_adst[(size_t)(r_g + 8) * HEADS + h0 + 1] = pd[1][1] * LOG2E;
                }
            }
        }
    }
}

// ---------------- gather v2: one warp per dst node, 2 edges/step, 8 ch/lane ----------------
__global__ void __launch_bounds__(256) gather_kernel(int N)
{
    int node = (blockIdx.x * blockDim.x + threadIdx.x) >> 5;
    if (node >= N) return;
    const int lane = threadIdx.x & 31;
    const int sub  = lane & 15;        // channel group
    const int half = lane >> 4;        // edge parity within a step pair
    const int head = sub >> 2;
    const int chan = sub * 8;

    const int off = g_off[node];
    const int deg = g_deg[node];

    const float ad_my = __ldg(&g_adst[(size_t)node * HEADS + head]);

    float acc[8];
#pragma unroll
    for (int c = 0; c < 8; ++c) acc[c] = 0.f;
    float s_my = 0.f;

    for (int base = 0; base < deg; base += 32) {
        int idx = 0;
        if (base + lane < deg) idx = g_srcs[off + base + lane];
        int cnt = min(32, deg - base);
        for (int j = 0; j < cnt; j += 4) {
            int e0 = j + half;
            int e1 = j + 2 + half;
            int s0 = __shfl_sync(0xFFFFFFFFu, idx, e0);
            int s1 = __shfl_sync(0xFFFFFFFFu, idx, e1);
            float as0 = __ldg(&g_asrc[(size_t)s0 * HEADS + head]);
            float as1 = __ldg(&g_asrc[(size_t)s1 * HEADS + head]);
            uint4 u0 = *reinterpret_cast<const uint4*>(&g_h[(size_t)s0 * CH + chan]);
            uint4 u1 = *reinterpret_cast<const uint4*>(&g_h[(size_t)s1 * CH + chan]);

            float x0 = (e0 < cnt) ? ex2f(lrelu(as0 + ad_my)) : 0.f;
            float x1 = (e1 < cnt) ? ex2f(lrelu(as1 + ad_my)) : 0.f;

            float2 f;
            f = __half22float2(*reinterpret_cast<__half2*>(&u0.x));
            acc[0] = fmaf(x0, f.x, acc[0]); acc[1] = fmaf(x0, f.y, acc[1]);
            f = __half22float2(*reinterpret_cast<__half2*>(&u0.y));
            acc[2] = fmaf(x0, f.x, acc[2]); acc[3] = fmaf(x0, f.y, acc[3]);
            f = __half22float2(*reinterpret_cast<__half2*>(&u0.z));
            acc[4] = fmaf(x0, f.x, acc[4]); acc[5] = fmaf(x0, f.y, acc[5]);
            f = __half22float2(*reinterpret_cast<__half2*>(&u0.w));
            acc[6] = fmaf(x0, f.x, acc[6]); acc[7] = fmaf(x0, f.y, acc[7]);

            f = __half22float2(*reinterpret_cast<__half2*>(&u1.x));
            acc[0] = fmaf(x1, f.x, acc[0]); acc[1] = fmaf(x1, f.y, acc[1]);
            f = __half22float2(*reinterpret_cast<__half2*>(&u1.y));
            acc[2] = fmaf(x1, f.x, acc[2]); acc[3] = fmaf(x1, f.y, acc[3]);
            f = __half22float2(*reinterpret_cast<__half2*>(&u1.z));
            acc[4] = fmaf(x1, f.x, acc[4]); acc[5] = fmaf(x1, f.y, acc[5]);
            f = __half22float2(*reinterpret_cast<__half2*>(&u1.w));
            acc[6] = fmaf(x1, f.x, acc[6]); acc[7] = fmaf(x1, f.y, acc[7]);

            s_my += x0 + x1;
        }
    }

#pragma unroll
    for (int c = 0; c < 8; ++c)
        acc[c] += __shfl_xor_sync(0xFFFFFFFFu, acc[c], 16);
    s_my += __shfl_xor_sync(0xFFFFFFFFu, s_my, 16);

    if (half == 0) {
        float inv = 1.f / (s_my + 1e-16f);
        float4 o0 = make_float4(acc[0] * inv, acc[1] * inv, acc[2] * inv, acc[3] * inv);
        float4 o1 = make_float4(acc[4] * inv, acc[5] * inv, acc[6] * inv, acc[7] * inv);
        float* dst = &g_accum[(size_t)node * CH + chan];
        *reinterpret_cast<float4*>(dst)     = o0;
        *reinterpret_cast<float4*>(dst + 4) = o1;
    }
}

// ---------------- launch ----------------
extern "C" void kernel_launch(void* const* d_in, const int* in_sizes, int n_in,
                              void* d_out, int out_size)
{
    const float* x     = (const float*)d_in[0];
    const int*   ei    = (const int*)  d_in[1];
    const float* W     = (const float*)d_in[2];
    const float* att_s = (const float*)d_in[3];
    const float* att_d = (const float*)d_in[4];
    const float* lin_w = (const float*)d_in[5];
    const float* lin_b = (const float*)d_in[6];
    float* out = (float*)d_out;

    int N = in_sizes[0] / CH;    // 100000
    int E = in_sizes[1] / 2;     // 1600000

    void *p_h, *p_acc, *p_whi, *p_wlo, *p_lwhi, *p_lwlo;
    cudaGetSymbolAddress(&p_h, g_h);
    cudaGetSymbolAddress(&p_acc, g_accum);
    cudaGetSymbolAddress(&p_whi, g_whi);
    cudaGetSymbolAddress(&p_wlo, g_wlo);
    cudaGetSymbolAddress(&p_lwhi, g_lwhi);
    cudaGetSymbolAddress(&p_lwlo, g_lwlo);

    const int SMEM = 98304;
    cudaFuncSetAttribute(gemm_mma<0>, cudaFuncAttributeMaxDynamicSharedMemorySize, SMEM);
    cudaFuncSetAttribute(gemm_mma<1>, cudaFuncAttributeMaxDynamicSharedMemorySize, SMEM);

    int ntiles = (N + 63) / 64;
    int gemm_blocks = (ntiles < 296) ? ntiles : 296;   // persistent, 2/SM

    // fork: csr_build (side stream) || prep + gemm1 (main stream) — proven topology
    cudaStream_t s2;
    cudaStreamCreateWithFlags(&s2, cudaStreamNonBlocking);
    cudaEvent_t ev_fork, ev_join;
    cudaEventCreateWithFlags(&ev_fork, cudaEventDisableTiming);
    cudaEventCreateWithFlags(&ev_join, cudaEventDisableTiming);

    cudaEventRecord(ev_fork, 0);
    cudaStreamWaitEvent(s2, ev_fork, 0);
    csr_build<<<NBLK, CBS, 0, s2>>>(ei, E, N);                                  // 0
    cudaEventRecord(ev_join, s2);

    prep_all<<<128, 256>>>(W, lin_w);                                           // 1
    gemm_mma<0><<<gemm_blocks, 256, SMEM>>>(                                    // 2
        x, (const unsigned char*)p_whi, (const unsigned char*)p_wlo,
        att_s, att_d, p_h, N);

    cudaStreamWaitEvent(0, ev_join, 0);
    gather_kernel<<<(N * 32 + 255) / 256, 256>>>(N);                            // 3 <- profiled
    gemm_mma<1><<<gemm_blocks, 256, SMEM>>>(                                    // 4
        (const float*)p_acc, (const unsigned char*)p_lwhi, (const unsigned char*)p_lwlo,
        lin_b, nullptr, out, N);
}